// round 9
// baseline (speedup 1.0000x reference)
#include <cuda_runtime.h>
#include <cuda_fp16.h>

#define NN 50000
#define EE 800000
#define E2 850000      // EE + NN self loops
#define HC 256
#define HEADS 4
#define HID 64
#define OUTD 86
#define SCAN_BLK 256
#define NBLK_SCAN ((NN + SCAN_BLK - 1) / SCAN_BLK)   // 196

// GEMM tiling: 128x128 block tile (2 heads), 8 warps of 32x64
#define BM 128
#define BNT 128
#define BK 32
#define ASTRIDE 36
#define BSTRIDE 136
#define ASZ (BM * ASTRIDE)
#define BSZ (BK * BSTRIDE)
#define GEMM_SMEM ((2 * ASZ + 2 * BSZ) * 4)

// ---- scratch (device globals: allocation-free) ----
__device__ __half g_h[NN * HC];         // post-GEMM features, fp16
__device__ float g_agg[NN * HC];
__device__ float g_as[NN * HEADS];
__device__ float g_ad[NN * HEADS];
__device__ float g_y[NN * HID];
__device__ float g_stats[2 * HC];
__device__ float g_scale[HC];
__device__ float g_shift[HC];
__device__ int   g_src[E2];
__device__ int   g_dst[E2];
__device__ int   g_rank[E2];
__device__ int   g_deg[NN];
__device__ int   g_off[NN + 1];
__device__ int   g_bsum[SCAN_BLK];
__device__ int   g_boff[SCAN_BLK];
__device__ int   g_csr[E2];
__device__ int   g_is64;

// ---------------- dtype probe + zero degree array (single block) ----------------
__global__ void detect_dtype(const int* __restrict__ ei32) {
    __shared__ int any;
    int t = threadIdx.x;
    if (t == 0) any = 0;
    __syncthreads();
    if (ei32[2 * t + 1] != 0) any = 1;
    for (int i = t; i < NN; i += 256) g_deg[i] = 0;
    __syncthreads();
    if (t == 0) g_is64 = !any;
}

// ---------------- normalize edge index + self loops + degree histogram ----------------
__global__ void convert_hist(const void* __restrict__ eiv) {
    int e = blockIdx.x * blockDim.x + threadIdx.x;
    if (e >= E2) return;
    int s, d;
    if (e >= EE) {
        s = d = e - EE;
    } else if (g_is64) {
        const long long* p = (const long long*)eiv;
        s = (int)p[e];
        d = (int)p[EE + e];
    } else {
        const int* p = (const int*)eiv;
        s = p[e];
        d = p[EE + e];
    }
    g_src[e] = s;
    g_dst[e] = d;
    g_rank[e] = atomicAdd(&g_deg[d], 1);
}

__global__ void scan1() {
    __shared__ int sh[SCAN_BLK];
    int t = threadIdx.x, b = blockIdx.x;
    int idx = b * SCAN_BLK + t;
    sh[t] = (idx < NN) ? g_deg[idx] : 0;
    __syncthreads();
    for (int o = 128; o > 0; o >>= 1) {
        if (t < o) sh[t] += sh[t + o];
        __syncthreads();
    }
    if (t == 0) g_bsum[b] = sh[0];
}

__global__ void scan2() {
    __shared__ int sh[SCAN_BLK];
    int t = threadIdx.x;
    sh[t] = (t < NBLK_SCAN) ? g_bsum[t] : 0;
    __syncthreads();
    int v = sh[t];
    for (int o = 1; o < SCAN_BLK; o <<= 1) {
        int u = (t >= o) ? sh[t - o] : 0;
        __syncthreads();
        sh[t] += u;
        __syncthreads();
    }
    g_boff[t] = sh[t] - v;
    if (t == 0) g_off[NN] = E2;
}

__global__ void scan3() {
    __shared__ int sh[SCAN_BLK];
    int t = threadIdx.x, b = blockIdx.x;
    int idx = b * SCAN_BLK + t;
    int v = (idx < NN) ? g_deg[idx] : 0;
    sh[t] = v;
    __syncthreads();
    for (int o = 1; o < SCAN_BLK; o <<= 1) {
        int u = (t >= o) ? sh[t - o] : 0;
        __syncthreads();
        sh[t] += u;
        __syncthreads();
    }
    if (idx < NN) g_off[idx] = g_boff[b] + sh[t] - v;
}

__global__ void scatter_csr() {
    int e = blockIdx.x * blockDim.x + threadIdx.x;
    if (e >= E2) return;
    g_csr[g_off[g_dst[e]] + g_rank[e]] = g_src[e];
}

// ---------------- TF32 GEMM 128x128 + fused BN/PReLU pre-op + attn epilogue ----------------
__device__ __forceinline__ unsigned f2tf(float x) {
    unsigned r;
    asm("cvt.rna.tf32.f32 %0, %1;" : "=r"(r) : "f"(x));
    return r;
}

__global__ __launch_bounds__(256) void gemm_tf32(
        const float* __restrict__ A, const float* __restrict__ B,
        __half* __restrict__ C, const float* __restrict__ attS,
        const float* __restrict__ attD, int M,
        const float* __restrict__ scale, const float* __restrict__ shift,
        const float* __restrict__ pw) {
    extern __shared__ float sm[];
    float* sA = sm;
    float* sB = sm + 2 * ASZ;
    const int K = 256;
    int tid = threadIdx.x, lane = tid & 31, warp = tid >> 5;
    int wm = warp >> 1, wn = warp & 1;   // 4x2 warps, 32x64 per warp
    int g = lane >> 2, tg = lane & 3;
    int rowBase = blockIdx.y * BM;
    int colBase = blockIdx.x * BNT;
    int head = blockIdx.x * 2 + wn;      // each warp owns a full head
    float w = scale ? pw[0] : 0.f;

    float acc[2][8][4];
    #pragma unroll
    for (int mt = 0; mt < 2; mt++)
        #pragma unroll
        for (int nt = 0; nt < 8; nt++)
            #pragma unroll
            for (int i = 0; i < 4; i++) acc[mt][nt][i] = 0.f;

    float4 av[4], bv[4];
    auto loadA = [&](int k0) {
        #pragma unroll
        for (int i = 0; i < 4; i++) {
            int F = tid + i * 256;
            int r = rowBase + (F >> 3);
            int c = (F & 7) * 4;
            if (r < M) {
                float4 v = *(const float4*)(A + (long)r * K + k0 + c);
                if (scale) {
                    float4 sc = *(const float4*)(scale + k0 + c);
                    float4 sh = *(const float4*)(shift + k0 + c);
                    v.x = fmaf(v.x, sc.x, sh.x); v.x = (v.x >= 0.f) ? v.x : w * v.x;
                    v.y = fmaf(v.y, sc.y, sh.y); v.y = (v.y >= 0.f) ? v.y : w * v.y;
                    v.z = fmaf(v.z, sc.z, sh.z); v.z = (v.z >= 0.f) ? v.z : w * v.z;
                    v.w = fmaf(v.w, sc.w, sh.w); v.w = (v.w >= 0.f) ? v.w : w * v.w;
                }
                av[i] = v;
            } else {
                av[i] = make_float4(0.f, 0.f, 0.f, 0.f);
            }
        }
        #pragma unroll
        for (int i = 0; i < 4; i++) {
            int F = tid + i * 256;
            int r = k0 + (F >> 5);
            int c = colBase + (F & 31) * 4;
            bv[i] = *(const float4*)(B + (long)r * HC + c);
        }
    };
    auto storeT = [&](int buf) {
        float* pA = sA + buf * ASZ;
        #pragma unroll
        for (int i = 0; i < 4; i++) {
            int F = tid + i * 256;
            int r = F >> 3, c = (F & 7) * 4;
            float4 v;
            v.x = __uint_as_float(f2tf(av[i].x));
            v.y = __uint_as_float(f2tf(av[i].y));
            v.z = __uint_as_float(f2tf(av[i].z));
            v.w = __uint_as_float(f2tf(av[i].w));
            *(float4*)(pA + r * ASTRIDE + c) = v;
        }
        float* pB = sB + buf * BSZ;
        #pragma unroll
        for (int i = 0; i < 4; i++) {
            int F = tid + i * 256;
            int r = F >> 5, c = (F & 31) * 4;
            float4 v;
            v.x = __uint_as_float(f2tf(bv[i].x));
            v.y = __uint_as_float(f2tf(bv[i].y));
            v.z = __uint_as_float(f2tf(bv[i].z));
            v.w = __uint_as_float(f2tf(bv[i].w));
            *(float4*)(pB + r * BSTRIDE + c) = v;
        }
    };

    loadA(0);
    storeT(0);
    __syncthreads();

    const int iters = K / BK;
    for (int it = 0; it < iters; it++) {
        int buf = it & 1;
        if (it + 1 < iters) loadA((it + 1) * BK);
        const float* pA = sA + buf * ASZ;
        const float* pB = sB + buf * BSZ;
        #pragma unroll
        for (int ks = 0; ks < 4; ks++) {
            int k = ks * 8;
            unsigned a[2][4], b[8][2];
            #pragma unroll
            for (int mt = 0; mt < 2; mt++) {
                int r0 = wm * 32 + mt * 16;
                a[mt][0] = __float_as_uint(pA[(r0 + g) * ASTRIDE + k + tg]);
                a[mt][1] = __float_as_uint(pA[(r0 + g + 8) * ASTRIDE + k + tg]);
                a[mt][2] = __float_as_uint(pA[(r0 + g) * ASTRIDE + k + tg + 4]);
                a[mt][3] = __float_as_uint(pA[(r0 + g + 8) * ASTRIDE + k + tg + 4]);
            }
            #pragma unroll
            for (int nt = 0; nt < 8; nt++) {
                int c0 = wn * 64 + nt * 8;
                b[nt][0] = __float_as_uint(pB[(k + tg) * BSTRIDE + c0 + g]);
                b[nt][1] = __float_as_uint(pB[(k + tg + 4) * BSTRIDE + c0 + g]);
            }
            #pragma unroll
            for (int mt = 0; mt < 2; mt++)
                #pragma unroll
                for (int nt = 0; nt < 8; nt++) {
                    asm volatile(
                        "mma.sync.aligned.m16n8k8.row.col.f32.tf32.tf32.f32 "
                        "{%0,%1,%2,%3}, {%4,%5,%6,%7}, {%8,%9}, {%0,%1,%2,%3};"
                        : "+f"(acc[mt][nt][0]), "+f"(acc[mt][nt][1]),
                          "+f"(acc[mt][nt][2]), "+f"(acc[mt][nt][3])
                        : "r"(a[mt][0]), "r"(a[mt][1]), "r"(a[mt][2]), "r"(a[mt][3]),
                          "r"(b[nt][0]), "r"(b[nt][1]));
                }
        }
        if (it + 1 < iters) storeT(buf ^ 1);
        __syncthreads();
    }

    // ---- C store (fp16) ----
    #pragma unroll
    for (int mt = 0; mt < 2; mt++) {
        int r = rowBase + wm * 32 + mt * 16 + g;
        #pragma unroll
        for (int nt = 0; nt < 8; nt++) {
            int c = colBase + wn * 64 + nt * 8 + tg * 2;
            if (r < M)
                *(__half2*)(C + (long)r * HC + c) =
                    __floats2half2_rn(acc[mt][nt][0], acc[mt][nt][1]);
            if (r + 8 < M)
                *(__half2*)(C + (long)(r + 8) * HC + c) =
                    __floats2half2_rn(acc[mt][nt][2], acc[mt][nt][3]);
        }
    }

    // ---- fused attention scores: warp-local (each warp owns one head) ----
    float ps0[2] = {0.f, 0.f}, ps1[2] = {0.f, 0.f};
    float pd0[2] = {0.f, 0.f}, pd1[2] = {0.f, 0.f};
    #pragma unroll
    for (int nt = 0; nt < 8; nt++) {
        int lc = nt * 8 + tg * 2;         // column within head
        float s0 = attS[head * HID + lc], s1 = attS[head * HID + lc + 1];
        float d0 = attD[head * HID + lc], d1 = attD[head * HID + lc + 1];
        #pragma unroll
        for (int mt = 0; mt < 2; mt++) {
            ps0[mt] += acc[mt][nt][0] * s0 + acc[mt][nt][1] * s1;
            ps1[mt] += acc[mt][nt][2] * s0 + acc[mt][nt][3] * s1;
            pd0[mt] += acc[mt][nt][0] * d0 + acc[mt][nt][1] * d1;
            pd1[mt] += acc[mt][nt][2] * d0 + acc[mt][nt][3] * d1;
        }
    }
    #pragma unroll
    for (int o = 1; o <= 2; o <<= 1) {
        #pragma unroll
        for (int mt = 0; mt < 2; mt++) {
            ps0[mt] += __shfl_xor_sync(0xffffffffu, ps0[mt], o);
            ps1[mt] += __shfl_xor_sync(0xffffffffu, ps1[mt], o);
            pd0[mt] += __shfl_xor_sync(0xffffffffu, pd0[mt], o);
            pd1[mt] += __shfl_xor_sync(0xffffffffu, pd1[mt], o);
        }
    }
    if (tg == 0) {
        #pragma unroll
        for (int mt = 0; mt < 2; mt++) {
            int r = rowBase + wm * 32 + mt * 16 + g;
            if (r < M) {
                g_as[r * HEADS + head] = ps0[mt];
                g_ad[r * HEADS + head] = pd0[mt];
            }
            if (r + 8 < M) {
                g_as[(r + 8) * HEADS + head] = ps1[mt];
                g_ad[(r + 8) * HEADS + head] = pd1[mt];
            }
        }
    }
}

// ---------------- CSR aggregation: single pass, TWO warps per dst node ----------------
__device__ __forceinline__ void fma8(float* a, float al, uint4 v) {
    float2 f0 = __half22float2(*(__half2*)&v.x);
    float2 f1 = __half22float2(*(__half2*)&v.y);
    float2 f2 = __half22float2(*(__half2*)&v.z);
    float2 f3 = __half22float2(*(__half2*)&v.w);
    a[0] = fmaf(al, f0.x, a[0]); a[1] = fmaf(al, f0.y, a[1]);
    a[2] = fmaf(al, f1.x, a[2]); a[3] = fmaf(al, f1.y, a[3]);
    a[4] = fmaf(al, f2.x, a[4]); a[5] = fmaf(al, f2.y, a[5]);
    a[6] = fmaf(al, f3.x, a[6]); a[7] = fmaf(al, f3.y, a[7]);
}

__global__ __launch_bounds__(256) void agg_csr(const __half* __restrict__ hsrc,
                                               float* __restrict__ outp,
                                               int meanHeads) {
    __shared__ float sAcc[4][256];
    __shared__ float sDen[4][4];
    // fold BN-stats zeroing into this kernel (completes before bn_stats launches)
    if (blockIdx.x == 0) {
        g_stats[threadIdx.x] = 0.f;
        g_stats[threadIdx.x + 256] = 0.f;
    }
    int warp = threadIdx.x >> 5;
    int lane = threadIdx.x & 31;
    int p = warp >> 1;                  // node slot in block (0..3)
    int sub = warp & 1;                 // edge-parity split
    int d = blockIdx.x * 4 + p;         // NN = 50000 = 4 * 12500 exactly
    int start = g_off[d], end = g_off[d + 1];
    int hh = lane >> 3;                 // lane covers channels [lane*8, lane*8+8)
    float dvh = g_ad[d * HEADS + hh];
    // single pass over this warp's half of the edges (stride 2, unroll 2)
    float den = 0.f;
    float a[8] = {0.f, 0.f, 0.f, 0.f, 0.f, 0.f, 0.f, 0.f};
    int e = start + sub;
    for (; e + 2 < end; e += 4) {
        int s0 = g_csr[e], s1 = g_csr[e + 2];
        float l0 = g_as[s0 * HEADS + hh] + dvh;
        float l1 = g_as[s1 * HEADS + hh] + dvh;
        uint4 v0 = *((const uint4*)(hsrc + (long)s0 * HC) + lane);
        uint4 v1 = *((const uint4*)(hsrc + (long)s1 * HC) + lane);
        l0 = fmaxf(l0, 0.2f * l0); float w0 = __expf(l0);
        l1 = fmaxf(l1, 0.2f * l1); float w1 = __expf(l1);
        den += w0 + w1;
        fma8(a, w0, v0);
        fma8(a, w1, v1);
    }
    if (e < end) {
        int s0 = g_csr[e];
        float l0 = g_as[s0 * HEADS + hh] + dvh;
        uint4 v0 = *((const uint4*)(hsrc + (long)s0 * HC) + lane);
        l0 = fmaxf(l0, 0.2f * l0);
        float w0 = __expf(l0);
        den += w0;
        fma8(a, w0, v0);
    }
    // combine sub-warp partials via smem
    if (sub == 1) {
        #pragma unroll
        for (int j = 0; j < 8; j++) sAcc[p][lane * 8 + j] = a[j];
        if ((lane & 7) == 0) sDen[p][hh] = den;
    }
    __syncthreads();
    if (sub == 1) return;
    #pragma unroll
    for (int j = 0; j < 8; j++) a[j] += sAcc[p][lane * 8 + j];
    den += sDen[p][hh];
    float invh = 1.f / (den + 1e-16f);
    #pragma unroll
    for (int j = 0; j < 8; j++) a[j] *= invh;
    if (!meanHeads) {
        float4* op = (float4*)(outp + (long)d * HC) + lane * 2;
        op[0] = make_float4(a[0], a[1], a[2], a[3]);
        op[1] = make_float4(a[4], a[5], a[6], a[7]);
    } else {
        // mean over heads: lanes L, L^8, L^16, L^24 hold same local channels
        #pragma unroll
        for (int j = 0; j < 8; j++) {
            a[j] += __shfl_xor_sync(0xffffffffu, a[j], 8);
            a[j] += __shfl_xor_sync(0xffffffffu, a[j], 16);
        }
        if (lane < 8) {
            float4* op = (float4*)(outp + (long)d * HID) + lane * 2;
            op[0] = make_float4(0.25f * a[0], 0.25f * a[1], 0.25f * a[2], 0.25f * a[3]);
            op[1] = make_float4(0.25f * a[4], 0.25f * a[5], 0.25f * a[6], 0.25f * a[7]);
        }
    }
}

__global__ void bn_stats(const float* __restrict__ x, int N, int C) {
    int tid = threadIdx.x;
    int c = tid % C;
    int g = tid / C;
    int G = blockDim.x / C;
    int rows_per_block = (N + gridDim.x - 1) / gridDim.x;
    int r0 = blockIdx.x * rows_per_block;
    int r1 = min(N, r0 + rows_per_block);
    float s = 0.f, q = 0.f;
    for (int r = r0 + g; r < r1; r += G) {
        float v = x[(long)r * C + c];
        s += v;
        q += v * v;
    }
    __shared__ float sh[512];
    sh[tid] = s;
    sh[256 + tid] = q;
    __syncthreads();
    if (g == 0) {
        for (int gg = 1; gg < G; gg++) {
            s += sh[gg * C + c];
            q += sh[256 + gg * C + c];
        }
        atomicAdd(&g_stats[c], s);
        atomicAdd(&g_stats[C + c], q);
    }
}

__global__ void bn_finalize(const float* __restrict__ gamma,
                            const float* __restrict__ beta, int N, int C) {
    int c = threadIdx.x;
    if (c >= C) return;
    float invN = 1.f / (float)N;
    float mean = g_stats[c] * invN;
    float var = g_stats[C + c] * invN - mean * mean;
    float sc = gamma[c] * rsqrtf(var + 1e-5f);
    g_scale[c] = sc;
    g_shift[c] = beta[c] - mean * sc;
}

__global__ void bn_apply_elu(float* __restrict__ x, const float* __restrict__ gamma,
                             const float* __restrict__ beta, int N, int C) {
    int i = blockIdx.x * blockDim.x + threadIdx.x;
    if (i >= N * C) return;
    int c = i % C;
    float invN = 1.f / (float)N;
    float mean = g_stats[c] * invN;
    float var = g_stats[C + c] * invN - mean * mean;
    float inv = rsqrtf(var + 1e-5f);
    float v = (x[i] - mean) * inv * gamma[c] + beta[c];
    v = (v > 0.f) ? v : expm1f(v);
    x[i] = v;
}

__global__ void fc_out(const float* __restrict__ W, const float* __restrict__ b,
                       float* __restrict__ out) {
    __shared__ float sW[HID * OUTD];
    for (int l = threadIdx.x; l < HID * OUTD; l += blockDim.x)
        sW[l] = W[l];
    __syncthreads();
    int i = blockIdx.x * blockDim.x + threadIdx.x;
    if (i >= NN * OUTD) return;
    int n = i / OUTD, o = i - n * OUTD;
    const float4* y4 = (const float4*)(g_y + (long)n * HID);
    float acc = b[o];
    #pragma unroll
    for (int k = 0; k < 16; k++) {
        float4 v = y4[k];
        acc += v.x * sW[(4 * k) * OUTD + o];
        acc += v.y * sW[(4 * k + 1) * OUTD + o];
        acc += v.z * sW[(4 * k + 2) * OUTD + o];
        acc += v.w * sW[(4 * k + 3) * OUTD + o];
    }
    out[i] = acc;
}

extern "C" void kernel_launch(void* const* d_in, const int* in_sizes, int n_in,
                              void* d_out, int out_size) {
    const float* x   = (const float*)d_in[0];
    const void*  ei  = d_in[1];
    const float* W1  = (const float*)d_in[2];
    const float* as1 = (const float*)d_in[3];
    const float* ad1 = (const float*)d_in[4];
    const float* W2  = (const float*)d_in[6];
    const float* as2 = (const float*)d_in[7];
    const float* ad2 = (const float*)d_in[8];
    const float* g1  = (const float*)d_in[10];
    const float* be1 = (const float*)d_in[11];
    const float* g2  = (const float*)d_in[12];
    const float* be2 = (const float*)d_in[13];
    const float* pw  = (const float*)d_in[14];
    const float* fcW = (const float*)d_in[15];
    const float* fcb = (const float*)d_in[16];
    float* out = (float*)d_out;

    __half* p_h;
    float *p_agg, *p_y, *p_scale, *p_shift;
    cudaGetSymbolAddress((void**)&p_h, g_h);
    cudaGetSymbolAddress((void**)&p_agg, g_agg);
    cudaGetSymbolAddress((void**)&p_y, g_y);
    cudaGetSymbolAddress((void**)&p_scale, g_scale);
    cudaGetSymbolAddress((void**)&p_shift, g_shift);

    static int smem_set = 0;
    if (!smem_set) {
        cudaFuncSetAttribute(gemm_tf32, cudaFuncAttributeMaxDynamicSharedMemorySize,
                             GEMM_SMEM);
        smem_set = 1;
    }

    dim3 gemmGrid(HC / BNT, (NN + BM - 1) / BM);   // (2, 391)
    int edgeBlocks = (E2 + 255) / 256;
    int aggBlocks  = NN / 4;                        // 12500, 2 warps per node

    // ---- CSR build ----
    detect_dtype<<<1, 256>>>((const int*)ei);
    convert_hist<<<edgeBlocks, 256>>>(ei);
    scan1<<<NBLK_SCAN, SCAN_BLK>>>();
    scan2<<<1, SCAN_BLK>>>();
    scan3<<<NBLK_SCAN, SCAN_BLK>>>();
    scatter_csr<<<edgeBlocks, 256>>>();

    // ---- layer 1 ----
    gemm_tf32<<<gemmGrid, 256, GEMM_SMEM>>>(x, W1, p_h, as1, ad1, NN,
                                            nullptr, nullptr, nullptr);
    agg_csr<<<aggBlocks, 256>>>(p_h, p_agg, 0);
    bn_stats<<<512, 256>>>(p_agg, NN, HC);
    bn_finalize<<<1, 256>>>(g1, be1, NN, HC);

    // ---- layer 2 (BN1 affine + PReLU fused into A-load; head-mean fused into agg) ----
    gemm_tf32<<<gemmGrid, 256, GEMM_SMEM>>>(p_agg, W2, p_h, as2, ad2, NN,
                                            p_scale, p_shift, pw);
    agg_csr<<<aggBlocks, 256>>>(p_h, p_y, 1);
    bn_stats<<<512, 256>>>(p_y, NN, HID);
    bn_apply_elu<<<(NN * HID + 255) / 256, 256>>>(p_y, g2, be2, NN, HID);
    fc_out<<<(NN * OUTD + 255) / 256, 256>>>(fcW, fcb, out);
}

// round 10
// speedup vs baseline: 1.5332x; 1.5332x over previous
#include <cuda_runtime.h>
#include <cuda_fp16.h>

#define NN 50000
#define EE 800000
#define E2 850000      // EE + NN self loops
#define HC 256
#define HEADS 4
#define HID 64
#define OUTD 86

// GEMM tiling: 128x128 block tile (2 heads), 8 warps of 32x64
#define BM 128
#define BNT 128
#define BK 32
#define ASTRIDE 36
#define BSTRIDE 136
#define ASZ (BM * ASTRIDE)
#define BSZ (BK * BSTRIDE)
#define GEMM_SMEM ((2 * ASZ + 2 * BSZ) * 4)

// ---- scratch (device globals: allocation-free) ----
__device__ __half g_h[NN * HC];         // post-GEMM features, fp16
__device__ float g_agg[NN * HC];
__device__ float g_as[NN * HEADS];
__device__ float g_ad[NN * HEADS];
__device__ float g_y[NN * HID];
__device__ float g_stats[2 * HC];
__device__ float g_scale[HC];
__device__ float g_shift[HC];
__device__ int   g_src[E2];
__device__ int   g_dst[E2];
__device__ int   g_rank[E2];
__device__ int   g_deg[NN];
__device__ int   g_off[NN];
__device__ int   g_cursor;
__device__ int   g_csr[E2];
__device__ int   g_is64;

// ---------------- dtype probe + zero degree array + cursor (single block) ----------------
__global__ void detect_dtype(const int* __restrict__ ei32) {
    __shared__ int any;
    int t = threadIdx.x;
    if (t == 0) { any = 0; g_cursor = 0; }
    __syncthreads();
    if (ei32[2 * t + 1] != 0) any = 1;
    for (int i = t; i < NN; i += 256) g_deg[i] = 0;
    __syncthreads();
    if (t == 0) g_is64 = !any;
}

// ---------------- normalize edge index + self loops + degree histogram ----------------
__global__ void convert_hist(const void* __restrict__ eiv) {
    int e = blockIdx.x * blockDim.x + threadIdx.x;
    if (e >= E2) return;
    int s, d;
    if (e >= EE) {
        s = d = e - EE;
    } else if (g_is64) {
        const long long* p = (const long long*)eiv;
        s = (int)p[e];
        d = (int)p[EE + e];
    } else {
        const int* p = (const int*)eiv;
        s = p[e];
        d = p[EE + e];
    }
    g_src[e] = s;
    g_dst[e] = d;
    g_rank[e] = atomicAdd(&g_deg[d], 1);
}

// ---------------- bump-allocator offsets (no scan needed) ----------------
__global__ void alloc_off() {
    int n = blockIdx.x * blockDim.x + threadIdx.x;
    if (n >= NN) return;
    g_off[n] = atomicAdd(&g_cursor, g_deg[n]);
}

__global__ void scatter_csr() {
    int e = blockIdx.x * blockDim.x + threadIdx.x;
    if (e >= E2) return;
    g_csr[g_off[g_dst[e]] + g_rank[e]] = g_src[e];
}

// ---------------- TF32 GEMM 128x128 + fused BN/PReLU pre-op + attn epilogue ----------------
__device__ __forceinline__ unsigned f2tf(float x) {
    unsigned r;
    asm("cvt.rna.tf32.f32 %0, %1;" : "=r"(r) : "f"(x));
    return r;
}

__global__ __launch_bounds__(256) void gemm_tf32(
        const float* __restrict__ A, const float* __restrict__ B,
        __half* __restrict__ C, const float* __restrict__ attS,
        const float* __restrict__ attD, int M,
        const float* __restrict__ scale, const float* __restrict__ shift,
        const float* __restrict__ pw) {
    extern __shared__ float sm[];
    float* sA = sm;
    float* sB = sm + 2 * ASZ;
    const int K = 256;
    int tid = threadIdx.x, lane = tid & 31, warp = tid >> 5;
    int wm = warp >> 1, wn = warp & 1;   // 4x2 warps, 32x64 per warp
    int g = lane >> 2, tg = lane & 3;
    int rowBase = blockIdx.y * BM;
    int colBase = blockIdx.x * BNT;
    int head = blockIdx.x * 2 + wn;      // each warp owns a full head
    float w = scale ? pw[0] : 0.f;

    float acc[2][8][4];
    #pragma unroll
    for (int mt = 0; mt < 2; mt++)
        #pragma unroll
        for (int nt = 0; nt < 8; nt++)
            #pragma unroll
            for (int i = 0; i < 4; i++) acc[mt][nt][i] = 0.f;

    float4 av[4], bv[4];
    auto loadA = [&](int k0) {
        #pragma unroll
        for (int i = 0; i < 4; i++) {
            int F = tid + i * 256;
            int r = rowBase + (F >> 3);
            int c = (F & 7) * 4;
            if (r < M) {
                float4 v = *(const float4*)(A + (long)r * K + k0 + c);
                if (scale) {
                    float4 sc = *(const float4*)(scale + k0 + c);
                    float4 sh = *(const float4*)(shift + k0 + c);
                    v.x = fmaf(v.x, sc.x, sh.x); v.x = (v.x >= 0.f) ? v.x : w * v.x;
                    v.y = fmaf(v.y, sc.y, sh.y); v.y = (v.y >= 0.f) ? v.y : w * v.y;
                    v.z = fmaf(v.z, sc.z, sh.z); v.z = (v.z >= 0.f) ? v.z : w * v.z;
                    v.w = fmaf(v.w, sc.w, sh.w); v.w = (v.w >= 0.f) ? v.w : w * v.w;
                }
                av[i] = v;
            } else {
                av[i] = make_float4(0.f, 0.f, 0.f, 0.f);
            }
        }
        #pragma unroll
        for (int i = 0; i < 4; i++) {
            int F = tid + i * 256;
            int r = k0 + (F >> 5);
            int c = colBase + (F & 31) * 4;
            bv[i] = *(const float4*)(B + (long)r * HC + c);
        }
    };
    auto storeT = [&](int buf) {
        float* pA = sA + buf * ASZ;
        #pragma unroll
        for (int i = 0; i < 4; i++) {
            int F = tid + i * 256;
            int r = F >> 3, c = (F & 7) * 4;
            float4 v;
            v.x = __uint_as_float(f2tf(av[i].x));
            v.y = __uint_as_float(f2tf(av[i].y));
            v.z = __uint_as_float(f2tf(av[i].z));
            v.w = __uint_as_float(f2tf(av[i].w));
            *(float4*)(pA + r * ASTRIDE + c) = v;
        }
        float* pB = sB + buf * BSZ;
        #pragma unroll
        for (int i = 0; i < 4; i++) {
            int F = tid + i * 256;
            int r = F >> 5, c = (F & 31) * 4;
            float4 v;
            v.x = __uint_as_float(f2tf(bv[i].x));
            v.y = __uint_as_float(f2tf(bv[i].y));
            v.z = __uint_as_float(f2tf(bv[i].z));
            v.w = __uint_as_float(f2tf(bv[i].w));
            *(float4*)(pB + r * BSTRIDE + c) = v;
        }
    };

    loadA(0);
    storeT(0);
    __syncthreads();

    const int iters = K / BK;
    for (int it = 0; it < iters; it++) {
        int buf = it & 1;
        if (it + 1 < iters) loadA((it + 1) * BK);
        const float* pA = sA + buf * ASZ;
        const float* pB = sB + buf * BSZ;
        #pragma unroll
        for (int ks = 0; ks < 4; ks++) {
            int k = ks * 8;
            unsigned a[2][4], b[8][2];
            #pragma unroll
            for (int mt = 0; mt < 2; mt++) {
                int r0 = wm * 32 + mt * 16;
                a[mt][0] = __float_as_uint(pA[(r0 + g) * ASTRIDE + k + tg]);
                a[mt][1] = __float_as_uint(pA[(r0 + g + 8) * ASTRIDE + k + tg]);
                a[mt][2] = __float_as_uint(pA[(r0 + g) * ASTRIDE + k + tg + 4]);
                a[mt][3] = __float_as_uint(pA[(r0 + g + 8) * ASTRIDE + k + tg + 4]);
            }
            #pragma unroll
            for (int nt = 0; nt < 8; nt++) {
                int c0 = wn * 64 + nt * 8;
                b[nt][0] = __float_as_uint(pB[(k + tg) * BSTRIDE + c0 + g]);
                b[nt][1] = __float_as_uint(pB[(k + tg + 4) * BSTRIDE + c0 + g]);
            }
            #pragma unroll
            for (int mt = 0; mt < 2; mt++)
                #pragma unroll
                for (int nt = 0; nt < 8; nt++) {
                    asm volatile(
                        "mma.sync.aligned.m16n8k8.row.col.f32.tf32.tf32.f32 "
                        "{%0,%1,%2,%3}, {%4,%5,%6,%7}, {%8,%9}, {%0,%1,%2,%3};"
                        : "+f"(acc[mt][nt][0]), "+f"(acc[mt][nt][1]),
                          "+f"(acc[mt][nt][2]), "+f"(acc[mt][nt][3])
                        : "r"(a[mt][0]), "r"(a[mt][1]), "r"(a[mt][2]), "r"(a[mt][3]),
                          "r"(b[nt][0]), "r"(b[nt][1]));
                }
        }
        if (it + 1 < iters) storeT(buf ^ 1);
        __syncthreads();
    }

    // ---- C store (fp16) ----
    #pragma unroll
    for (int mt = 0; mt < 2; mt++) {
        int r = rowBase + wm * 32 + mt * 16 + g;
        #pragma unroll
        for (int nt = 0; nt < 8; nt++) {
            int c = colBase + wn * 64 + nt * 8 + tg * 2;
            if (r < M)
                *(__half2*)(C + (long)r * HC + c) =
                    __floats2half2_rn(acc[mt][nt][0], acc[mt][nt][1]);
            if (r + 8 < M)
                *(__half2*)(C + (long)(r + 8) * HC + c) =
                    __floats2half2_rn(acc[mt][nt][2], acc[mt][nt][3]);
        }
    }

    // ---- fused attention scores: warp-local (each warp owns one head) ----
    float ps0[2] = {0.f, 0.f}, ps1[2] = {0.f, 0.f};
    float pd0[2] = {0.f, 0.f}, pd1[2] = {0.f, 0.f};
    #pragma unroll
    for (int nt = 0; nt < 8; nt++) {
        int lc = nt * 8 + tg * 2;         // column within head
        float s0 = attS[head * HID + lc], s1 = attS[head * HID + lc + 1];
        float d0 = attD[head * HID + lc], d1 = attD[head * HID + lc + 1];
        #pragma unroll
        for (int mt = 0; mt < 2; mt++) {
            ps0[mt] += acc[mt][nt][0] * s0 + acc[mt][nt][1] * s1;
            ps1[mt] += acc[mt][nt][2] * s0 + acc[mt][nt][3] * s1;
            pd0[mt] += acc[mt][nt][0] * d0 + acc[mt][nt][1] * d1;
            pd1[mt] += acc[mt][nt][2] * d0 + acc[mt][nt][3] * d1;
        }
    }
    #pragma unroll
    for (int o = 1; o <= 2; o <<= 1) {
        #pragma unroll
        for (int mt = 0; mt < 2; mt++) {
            ps0[mt] += __shfl_xor_sync(0xffffffffu, ps0[mt], o);
            ps1[mt] += __shfl_xor_sync(0xffffffffu, ps1[mt], o);
            pd0[mt] += __shfl_xor_sync(0xffffffffu, pd0[mt], o);
            pd1[mt] += __shfl_xor_sync(0xffffffffu, pd1[mt], o);
        }
    }
    if (tg == 0) {
        #pragma unroll
        for (int mt = 0; mt < 2; mt++) {
            int r = rowBase + wm * 32 + mt * 16 + g;
            if (r < M) {
                g_as[r * HEADS + head] = ps0[mt];
                g_ad[r * HEADS + head] = pd0[mt];
            }
            if (r + 8 < M) {
                g_as[(r + 8) * HEADS + head] = ps1[mt];
                g_ad[(r + 8) * HEADS + head] = pd1[mt];
            }
        }
    }
}

// ---------------- CSR aggregation: warp per dst node (R7 structure) ----------------
__device__ __forceinline__ void fma8(float* a, float al, uint4 v) {
    float2 f0 = __half22float2(*(__half2*)&v.x);
    float2 f1 = __half22float2(*(__half2*)&v.y);
    float2 f2 = __half22float2(*(__half2*)&v.z);
    float2 f3 = __half22float2(*(__half2*)&v.w);
    a[0] = fmaf(al, f0.x, a[0]); a[1] = fmaf(al, f0.y, a[1]);
    a[2] = fmaf(al, f1.x, a[2]); a[3] = fmaf(al, f1.y, a[3]);
    a[4] = fmaf(al, f2.x, a[4]); a[5] = fmaf(al, f2.y, a[5]);
    a[6] = fmaf(al, f3.x, a[6]); a[7] = fmaf(al, f3.y, a[7]);
}

__global__ void agg_csr(const __half* __restrict__ hsrc, float* __restrict__ outp,
                        int meanHeads) {
    // fold BN-stats zeroing into this kernel (completes before bn_stats launches)
    if (blockIdx.x == 0) {
        g_stats[threadIdx.x] = 0.f;
        g_stats[threadIdx.x + 256] = 0.f;
    }
    int d = (blockIdx.x * blockDim.x + threadIdx.x) >> 5;
    int lane = threadIdx.x & 31;
    if (d >= NN) return;
    int start = g_off[d], end = start + g_deg[d];
    float4 dv = *(const float4*)(g_ad + d * HEADS);
    float d0 = 0.f, d1 = 0.f, d2 = 0.f, d3 = 0.f;
    // pass 1: softmax denominator (warp-parallel over edges)
    for (int e = start + lane; e < end; e += 32) {
        int s = g_csr[e];
        float4 sv = *(const float4*)(g_as + s * HEADS);
        float l0 = sv.x + dv.x; l0 = fmaxf(l0, 0.2f * l0); d0 += __expf(l0);
        float l1 = sv.y + dv.y; l1 = fmaxf(l1, 0.2f * l1); d1 += __expf(l1);
        float l2 = sv.z + dv.z; l2 = fmaxf(l2, 0.2f * l2); d2 += __expf(l2);
        float l3 = sv.w + dv.w; l3 = fmaxf(l3, 0.2f * l3); d3 += __expf(l3);
    }
    #pragma unroll
    for (int o = 16; o > 0; o >>= 1) {
        d0 += __shfl_xor_sync(0xffffffffu, d0, o);
        d1 += __shfl_xor_sync(0xffffffffu, d1, o);
        d2 += __shfl_xor_sync(0xffffffffu, d2, o);
        d3 += __shfl_xor_sync(0xffffffffu, d3, o);
    }
    int hh = lane >> 3;            // lane covers channels [lane*8, lane*8+8)
    float dvh = (hh == 0) ? dv.x : (hh == 1) ? dv.y : (hh == 2) ? dv.z : dv.w;
    float den = (hh == 0) ? d0 : (hh == 1) ? d1 : (hh == 2) ? d2 : d3;
    float invh = 1.f / (den + 1e-16f);
    // pass 2: weighted gather (exp recomputed per lane), unroll 2
    float a[8] = {0.f, 0.f, 0.f, 0.f, 0.f, 0.f, 0.f, 0.f};
    int e = start;
    for (; e + 2 <= end; e += 2) {
        int s0 = g_csr[e], s1 = g_csr[e + 1];
        float l0 = g_as[s0 * HEADS + hh] + dvh;
        float l1 = g_as[s1 * HEADS + hh] + dvh;
        l0 = fmaxf(l0, 0.2f * l0);
        l1 = fmaxf(l1, 0.2f * l1);
        float w0 = __expf(l0), w1 = __expf(l1);
        uint4 v0 = *((const uint4*)(hsrc + (long)s0 * HC) + lane);
        uint4 v1 = *((const uint4*)(hsrc + (long)s1 * HC) + lane);
        fma8(a, w0, v0);
        fma8(a, w1, v1);
    }
    if (e < end) {
        int s0 = g_csr[e];
        float l0 = g_as[s0 * HEADS + hh] + dvh;
        l0 = fmaxf(l0, 0.2f * l0);
        uint4 v0 = *((const uint4*)(hsrc + (long)s0 * HC) + lane);
        fma8(a, __expf(l0), v0);
    }
    #pragma unroll
    for (int j = 0; j < 8; j++) a[j] *= invh;
    if (!meanHeads) {
        float4* op = (float4*)(outp + (long)d * HC) + lane * 2;
        op[0] = make_float4(a[0], a[1], a[2], a[3]);
        op[1] = make_float4(a[4], a[5], a[6], a[7]);
    } else {
        // mean over heads: lanes L, L^8, L^16, L^24 hold same local channels
        #pragma unroll
        for (int j = 0; j < 8; j++) {
            a[j] += __shfl_xor_sync(0xffffffffu, a[j], 8);
            a[j] += __shfl_xor_sync(0xffffffffu, a[j], 16);
        }
        if (lane < 8) {
            float4* op = (float4*)(outp + (long)d * HID) + lane * 2;
            op[0] = make_float4(0.25f * a[0], 0.25f * a[1], 0.25f * a[2], 0.25f * a[3]);
            op[1] = make_float4(0.25f * a[4], 0.25f * a[5], 0.25f * a[6], 0.25f * a[7]);
        }
    }
}

__global__ void bn_stats(const float* __restrict__ x, int N, int C) {
    int tid = threadIdx.x;
    int c = tid % C;
    int g = tid / C;
    int G = blockDim.x / C;
    int rows_per_block = (N + gridDim.x - 1) / gridDim.x;
    int r0 = blockIdx.x * rows_per_block;
    int r1 = min(N, r0 + rows_per_block);
    float s = 0.f, q = 0.f;
    for (int r = r0 + g; r < r1; r += G) {
        float v = x[(long)r * C + c];
        s += v;
        q += v * v;
    }
    __shared__ float sh[512];
    sh[tid] = s;
    sh[256 + tid] = q;
    __syncthreads();
    if (g == 0) {
        for (int gg = 1; gg < G; gg++) {
            s += sh[gg * C + c];
            q += sh[256 + gg * C + c];
        }
        atomicAdd(&g_stats[c], s);
        atomicAdd(&g_stats[C + c], q);
    }
}

__global__ void bn_finalize(const float* __restrict__ gamma,
                            const float* __restrict__ beta, int N, int C) {
    int c = threadIdx.x;
    if (c >= C) return;
    float invN = 1.f / (float)N;
    float mean = g_stats[c] * invN;
    float var = g_stats[C + c] * invN - mean * mean;
    float sc = gamma[c] * rsqrtf(var + 1e-5f);
    g_scale[c] = sc;
    g_shift[c] = beta[c] - mean * sc;
}

__global__ void bn_apply_elu(float* __restrict__ x, const float* __restrict__ gamma,
                             const float* __restrict__ beta, int N, int C) {
    int i = blockIdx.x * blockDim.x + threadIdx.x;
    if (i >= N * C) return;
    int c = i % C;
    float invN = 1.f / (float)N;
    float mean = g_stats[c] * invN;
    float var = g_stats[C + c] * invN - mean * mean;
    float inv = rsqrtf(var + 1e-5f);
    float v = (x[i] - mean) * inv * gamma[c] + beta[c];
    v = (v > 0.f) ? v : expm1f(v);
    x[i] = v;
}

__global__ void fc_out(const float* __restrict__ W, const float* __restrict__ b,
                       float* __restrict__ out) {
    __shared__ float sW[HID * OUTD];
    for (int l = threadIdx.x; l < HID * OUTD; l += blockDim.x)
        sW[l] = W[l];
    __syncthreads();
    int i = blockIdx.x * blockDim.x + threadIdx.x;
    if (i >= NN * OUTD) return;
    int n = i / OUTD, o = i - n * OUTD;
    const float4* y4 = (const float4*)(g_y + (long)n * HID);
    float acc = b[o];
    #pragma unroll
    for (int k = 0; k < 16; k++) {
        float4 v = y4[k];
        acc += v.x * sW[(4 * k) * OUTD + o];
        acc += v.y * sW[(4 * k + 1) * OUTD + o];
        acc += v.z * sW[(4 * k + 2) * OUTD + o];
        acc += v.w * sW[(4 * k + 3) * OUTD + o];
    }
    out[i] = acc;
}

extern "C" void kernel_launch(void* const* d_in, const int* in_sizes, int n_in,
                              void* d_out, int out_size) {
    const float* x   = (const float*)d_in[0];
    const void*  ei  = d_in[1];
    const float* W1  = (const float*)d_in[2];
    const float* as1 = (const float*)d_in[3];
    const float* ad1 = (const float*)d_in[4];
    const float* W2  = (const float*)d_in[6];
    const float* as2 = (const float*)d_in[7];
    const float* ad2 = (const float*)d_in[8];
    const float* g1  = (const float*)d_in[10];
    const float* be1 = (const float*)d_in[11];
    const float* g2  = (const float*)d_in[12];
    const float* be2 = (const float*)d_in[13];
    const float* pw  = (const float*)d_in[14];
    const float* fcW = (const float*)d_in[15];
    const float* fcb = (const float*)d_in[16];
    float* out = (float*)d_out;

    __half* p_h;
    float *p_agg, *p_y, *p_scale, *p_shift;
    cudaGetSymbolAddress((void**)&p_h, g_h);
    cudaGetSymbolAddress((void**)&p_agg, g_agg);
    cudaGetSymbolAddress((void**)&p_y, g_y);
    cudaGetSymbolAddress((void**)&p_scale, g_scale);
    cudaGetSymbolAddress((void**)&p_shift, g_shift);

    static int smem_set = 0;
    if (!smem_set) {
        cudaFuncSetAttribute(gemm_tf32, cudaFuncAttributeMaxDynamicSharedMemorySize,
                             GEMM_SMEM);
        smem_set = 1;
    }

    dim3 gemmGrid(HC / BNT, (NN + BM - 1) / BM);   // (2, 391)
    int edgeBlocks = (E2 + 255) / 256;
    int aggBlocks  = (NN * 32 + 255) / 256;

    // ---- CSR build (scan-free: bump allocator) ----
    detect_dtype<<<1, 256>>>((const int*)ei);
    convert_hist<<<edgeBlocks, 256>>>(ei);
    alloc_off<<<(NN + 255) / 256, 256>>>();
    scatter_csr<<<edgeBlocks, 256>>>();

    // ---- layer 1 ----
    gemm_tf32<<<gemmGrid, 256, GEMM_SMEM>>>(x, W1, p_h, as1, ad1, NN,
                                            nullptr, nullptr, nullptr);
    agg_csr<<<aggBlocks, 256>>>(p_h, p_agg, 0);
    bn_stats<<<512, 256>>>(p_agg, NN, HC);
    bn_finalize<<<1, 256>>>(g1, be1, NN, HC);

    // ---- layer 2 (BN1 affine + PReLU fused into A-load; head-mean fused into agg) ----
    gemm_tf32<<<gemmGrid, 256, GEMM_SMEM>>>(p_agg, W2, p_h, as2, ad2, NN,
                                            p_scale, p_shift, pw);
    agg_csr<<<aggBlocks, 256>>>(p_h, p_y, 1);
    bn_stats<<<512, 256>>>(p_y, NN, HID);
    bn_apply_elu<<<(NN * HID + 255) / 256, 256>>>(p_y, g2, be2, NN, HID);
    fc_out<<<(NN * OUTD + 255) / 256, 256>>>(fcW, fcb, out);
}

// round 11
// speedup vs baseline: 1.6027x; 1.0453x over previous
#include <cuda_runtime.h>
#include <cuda_fp16.h>

#define NN 50000
#define EE 800000
#define E2 850000      // EE + NN self loops
#define HC 256
#define HEADS 4
#define HID 64
#define OUTD 86

// GEMM tiling: 128x128 block tile (2 heads), 8 warps of 32x64
#define BM 128
#define BNT 128
#define BK 32
#define ASTRIDE 36
#define BSTRIDE 136
#define ASZ (BM * ASTRIDE)
#define BSZ (BK * BSTRIDE)
#define GEMM_SMEM ((2 * ASZ + 2 * BSZ) * 4)

// ---- scratch (device globals: allocation-free) ----
__device__ __half g_h[NN * HC];         // post-GEMM features, fp16
__device__ float g_agg[NN * HC];
__device__ float g_as[NN * HEADS];
__device__ float g_ad[NN * HEADS];
__device__ float g_y[NN * HID];
__device__ float g_stats[2 * HC];
__device__ float g_scale[HC];
__device__ float g_shift[HC];
__device__ int   g_src[E2];
__device__ int   g_dst[E2];
__device__ int   g_rank[E2];
__device__ int   g_deg[NN];
__device__ int   g_off[NN];
__device__ int   g_cursor;
__device__ int   g_csr[E2];
__device__ int   g_is64;

// ---------------- dtype probe + zero degree array + cursor (single block) ----------------
__global__ void detect_dtype(const int* __restrict__ ei32) {
    __shared__ int any;
    int t = threadIdx.x;
    if (t == 0) { any = 0; g_cursor = 0; }
    __syncthreads();
    if (ei32[2 * t + 1] != 0) any = 1;
    for (int i = t; i < NN; i += 256) g_deg[i] = 0;
    __syncthreads();
    if (t == 0) g_is64 = !any;
}

// ---------------- normalize edge index + self loops + degree histogram ----------------
__global__ void convert_hist(const void* __restrict__ eiv) {
    int e = blockIdx.x * blockDim.x + threadIdx.x;
    if (e >= E2) return;
    int s, d;
    if (e >= EE) {
        s = d = e - EE;
    } else if (g_is64) {
        const long long* p = (const long long*)eiv;
        s = (int)p[e];
        d = (int)p[EE + e];
    } else {
        const int* p = (const int*)eiv;
        s = p[e];
        d = p[EE + e];
    }
    g_src[e] = s;
    g_dst[e] = d;
    g_rank[e] = atomicAdd(&g_deg[d], 1);
}

// ---------------- bump-allocator offsets (no scan needed) ----------------
__global__ void alloc_off() {
    int n = blockIdx.x * blockDim.x + threadIdx.x;
    if (n >= NN) return;
    g_off[n] = atomicAdd(&g_cursor, g_deg[n]);
}

__global__ void scatter_csr() {
    int e = blockIdx.x * blockDim.x + threadIdx.x;
    if (e >= E2) return;
    g_csr[g_off[g_dst[e]] + g_rank[e]] = g_src[e];
}

// ---------------- TF32 GEMM 128x128 + fused BN/PReLU pre-op + attn epilogue ----------------
__device__ __forceinline__ unsigned f2tf(float x) {
    unsigned r;
    asm("cvt.rna.tf32.f32 %0, %1;" : "=r"(r) : "f"(x));
    return r;
}

__global__ __launch_bounds__(256) void gemm_tf32(
        const float* __restrict__ A, const float* __restrict__ B,
        __half* __restrict__ C, const float* __restrict__ attS,
        const float* __restrict__ attD, int M,
        const float* __restrict__ scale, const float* __restrict__ shift,
        const float* __restrict__ pw) {
    extern __shared__ float sm[];
    float* sA = sm;
    float* sB = sm + 2 * ASZ;
    const int K = 256;
    int tid = threadIdx.x, lane = tid & 31, warp = tid >> 5;
    int wm = warp >> 1, wn = warp & 1;   // 4x2 warps, 32x64 per warp
    int g = lane >> 2, tg = lane & 3;
    int rowBase = blockIdx.y * BM;
    int colBase = blockIdx.x * BNT;
    int head = blockIdx.x * 2 + wn;      // each warp owns a full head
    float w = scale ? pw[0] : 0.f;

    float acc[2][8][4];
    #pragma unroll
    for (int mt = 0; mt < 2; mt++)
        #pragma unroll
        for (int nt = 0; nt < 8; nt++)
            #pragma unroll
            for (int i = 0; i < 4; i++) acc[mt][nt][i] = 0.f;

    float4 av[4], bv[4];
    auto loadA = [&](int k0) {
        #pragma unroll
        for (int i = 0; i < 4; i++) {
            int F = tid + i * 256;
            int r = rowBase + (F >> 3);
            int c = (F & 7) * 4;
            if (r < M) {
                float4 v = *(const float4*)(A + (long)r * K + k0 + c);
                if (scale) {
                    float4 sc = *(const float4*)(scale + k0 + c);
                    float4 sh = *(const float4*)(shift + k0 + c);
                    v.x = fmaf(v.x, sc.x, sh.x); v.x = (v.x >= 0.f) ? v.x : w * v.x;
                    v.y = fmaf(v.y, sc.y, sh.y); v.y = (v.y >= 0.f) ? v.y : w * v.y;
                    v.z = fmaf(v.z, sc.z, sh.z); v.z = (v.z >= 0.f) ? v.z : w * v.z;
                    v.w = fmaf(v.w, sc.w, sh.w); v.w = (v.w >= 0.f) ? v.w : w * v.w;
                }
                av[i] = v;
            } else {
                av[i] = make_float4(0.f, 0.f, 0.f, 0.f);
            }
        }
        #pragma unroll
        for (int i = 0; i < 4; i++) {
            int F = tid + i * 256;
            int r = k0 + (F >> 5);
            int c = colBase + (F & 31) * 4;
            bv[i] = *(const float4*)(B + (long)r * HC + c);
        }
    };
    auto storeT = [&](int buf) {
        float* pA = sA + buf * ASZ;
        #pragma unroll
        for (int i = 0; i < 4; i++) {
            int F = tid + i * 256;
            int r = F >> 3, c = (F & 7) * 4;
            float4 v;
            v.x = __uint_as_float(f2tf(av[i].x));
            v.y = __uint_as_float(f2tf(av[i].y));
            v.z = __uint_as_float(f2tf(av[i].z));
            v.w = __uint_as_float(f2tf(av[i].w));
            *(float4*)(pA + r * ASTRIDE + c) = v;
        }
        float* pB = sB + buf * BSZ;
        #pragma unroll
        for (int i = 0; i < 4; i++) {
            int F = tid + i * 256;
            int r = F >> 5, c = (F & 31) * 4;
            float4 v;
            v.x = __uint_as_float(f2tf(bv[i].x));
            v.y = __uint_as_float(f2tf(bv[i].y));
            v.z = __uint_as_float(f2tf(bv[i].z));
            v.w = __uint_as_float(f2tf(bv[i].w));
            *(float4*)(pB + r * BSTRIDE + c) = v;
        }
    };

    loadA(0);
    storeT(0);
    __syncthreads();

    const int iters = K / BK;
    for (int it = 0; it < iters; it++) {
        int buf = it & 1;
        if (it + 1 < iters) loadA((it + 1) * BK);
        const float* pA = sA + buf * ASZ;
        const float* pB = sB + buf * BSZ;
        #pragma unroll
        for (int ks = 0; ks < 4; ks++) {
            int k = ks * 8;
            unsigned a[2][4], b[8][2];
            #pragma unroll
            for (int mt = 0; mt < 2; mt++) {
                int r0 = wm * 32 + mt * 16;
                a[mt][0] = __float_as_uint(pA[(r0 + g) * ASTRIDE + k + tg]);
                a[mt][1] = __float_as_uint(pA[(r0 + g + 8) * ASTRIDE + k + tg]);
                a[mt][2] = __float_as_uint(pA[(r0 + g) * ASTRIDE + k + tg + 4]);
                a[mt][3] = __float_as_uint(pA[(r0 + g + 8) * ASTRIDE + k + tg + 4]);
            }
            #pragma unroll
            for (int nt = 0; nt < 8; nt++) {
                int c0 = wn * 64 + nt * 8;
                b[nt][0] = __float_as_uint(pB[(k + tg) * BSTRIDE + c0 + g]);
                b[nt][1] = __float_as_uint(pB[(k + tg + 4) * BSTRIDE + c0 + g]);
            }
            #pragma unroll
            for (int mt = 0; mt < 2; mt++)
                #pragma unroll
                for (int nt = 0; nt < 8; nt++) {
                    asm volatile(
                        "mma.sync.aligned.m16n8k8.row.col.f32.tf32.tf32.f32 "
                        "{%0,%1,%2,%3}, {%4,%5,%6,%7}, {%8,%9}, {%0,%1,%2,%3};"
                        : "+f"(acc[mt][nt][0]), "+f"(acc[mt][nt][1]),
                          "+f"(acc[mt][nt][2]), "+f"(acc[mt][nt][3])
                        : "r"(a[mt][0]), "r"(a[mt][1]), "r"(a[mt][2]), "r"(a[mt][3]),
                          "r"(b[nt][0]), "r"(b[nt][1]));
                }
        }
        if (it + 1 < iters) storeT(buf ^ 1);
        __syncthreads();
    }

    // ---- C store (fp16) ----
    #pragma unroll
    for (int mt = 0; mt < 2; mt++) {
        int r = rowBase + wm * 32 + mt * 16 + g;
        #pragma unroll
        for (int nt = 0; nt < 8; nt++) {
            int c = colBase + wn * 64 + nt * 8 + tg * 2;
            if (r < M)
                *(__half2*)(C + (long)r * HC + c) =
                    __floats2half2_rn(acc[mt][nt][0], acc[mt][nt][1]);
            if (r + 8 < M)
                *(__half2*)(C + (long)(r + 8) * HC + c) =
                    __floats2half2_rn(acc[mt][nt][2], acc[mt][nt][3]);
        }
    }

    // ---- fused attention scores: warp-local (each warp owns one head) ----
    float ps0[2] = {0.f, 0.f}, ps1[2] = {0.f, 0.f};
    float pd0[2] = {0.f, 0.f}, pd1[2] = {0.f, 0.f};
    #pragma unroll
    for (int nt = 0; nt < 8; nt++) {
        int lc = nt * 8 + tg * 2;         // column within head
        float s0 = attS[head * HID + lc], s1 = attS[head * HID + lc + 1];
        float d0 = attD[head * HID + lc], d1 = attD[head * HID + lc + 1];
        #pragma unroll
        for (int mt = 0; mt < 2; mt++) {
            ps0[mt] += acc[mt][nt][0] * s0 + acc[mt][nt][1] * s1;
            ps1[mt] += acc[mt][nt][2] * s0 + acc[mt][nt][3] * s1;
            pd0[mt] += acc[mt][nt][0] * d0 + acc[mt][nt][1] * d1;
            pd1[mt] += acc[mt][nt][2] * d0 + acc[mt][nt][3] * d1;
        }
    }
    #pragma unroll
    for (int o = 1; o <= 2; o <<= 1) {
        #pragma unroll
        for (int mt = 0; mt < 2; mt++) {
            ps0[mt] += __shfl_xor_sync(0xffffffffu, ps0[mt], o);
            ps1[mt] += __shfl_xor_sync(0xffffffffu, ps1[mt], o);
            pd0[mt] += __shfl_xor_sync(0xffffffffu, pd0[mt], o);
            pd1[mt] += __shfl_xor_sync(0xffffffffu, pd1[mt], o);
        }
    }
    if (tg == 0) {
        #pragma unroll
        for (int mt = 0; mt < 2; mt++) {
            int r = rowBase + wm * 32 + mt * 16 + g;
            if (r < M) {
                g_as[r * HEADS + head] = ps0[mt];
                g_ad[r * HEADS + head] = pd0[mt];
            }
            if (r + 8 < M) {
                g_as[(r + 8) * HEADS + head] = ps1[mt];
                g_ad[(r + 8) * HEADS + head] = pd1[mt];
            }
        }
    }
}

// ---------------- CSR aggregation: warp per dst node (R7 structure) ----------------
__device__ __forceinline__ void fma8(float* a, float al, uint4 v) {
    float2 f0 = __half22float2(*(__half2*)&v.x);
    float2 f1 = __half22float2(*(__half2*)&v.y);
    float2 f2 = __half22float2(*(__half2*)&v.z);
    float2 f3 = __half22float2(*(__half2*)&v.w);
    a[0] = fmaf(al, f0.x, a[0]); a[1] = fmaf(al, f0.y, a[1]);
    a[2] = fmaf(al, f1.x, a[2]); a[3] = fmaf(al, f1.y, a[3]);
    a[4] = fmaf(al, f2.x, a[4]); a[5] = fmaf(al, f2.y, a[5]);
    a[6] = fmaf(al, f3.x, a[6]); a[7] = fmaf(al, f3.y, a[7]);
}

__global__ void agg_csr(const __half* __restrict__ hsrc, float* __restrict__ outp,
                        int meanHeads) {
    // fold BN-stats zeroing into this kernel (completes before bn_stats launches)
    if (blockIdx.x == 0) {
        g_stats[threadIdx.x] = 0.f;
        g_stats[threadIdx.x + 256] = 0.f;
    }
    int d = (blockIdx.x * blockDim.x + threadIdx.x) >> 5;
    int lane = threadIdx.x & 31;
    if (d >= NN) return;
    int start = g_off[d], end = start + g_deg[d];
    float4 dv = *(const float4*)(g_ad + d * HEADS);
    float d0 = 0.f, d1 = 0.f, d2 = 0.f, d3 = 0.f;
    // pass 1: softmax denominator (warp-parallel over edges)
    for (int e = start + lane; e < end; e += 32) {
        int s = g_csr[e];
        float4 sv = *(const float4*)(g_as + s * HEADS);
        float l0 = sv.x + dv.x; l0 = fmaxf(l0, 0.2f * l0); d0 += __expf(l0);
        float l1 = sv.y + dv.y; l1 = fmaxf(l1, 0.2f * l1); d1 += __expf(l1);
        float l2 = sv.z + dv.z; l2 = fmaxf(l2, 0.2f * l2); d2 += __expf(l2);
        float l3 = sv.w + dv.w; l3 = fmaxf(l3, 0.2f * l3); d3 += __expf(l3);
    }
    #pragma unroll
    for (int o = 16; o > 0; o >>= 1) {
        d0 += __shfl_xor_sync(0xffffffffu, d0, o);
        d1 += __shfl_xor_sync(0xffffffffu, d1, o);
        d2 += __shfl_xor_sync(0xffffffffu, d2, o);
        d3 += __shfl_xor_sync(0xffffffffu, d3, o);
    }
    int hh = lane >> 3;            // lane covers channels [lane*8, lane*8+8)
    float dvh = (hh == 0) ? dv.x : (hh == 1) ? dv.y : (hh == 2) ? dv.z : dv.w;
    float den = (hh == 0) ? d0 : (hh == 1) ? d1 : (hh == 2) ? d2 : d3;
    float invh = 1.f / (den + 1e-16f);
    // pass 2: weighted gather (exp recomputed per lane), unroll 2
    float a[8] = {0.f, 0.f, 0.f, 0.f, 0.f, 0.f, 0.f, 0.f};
    int e = start;
    for (; e + 2 <= end; e += 2) {
        int s0 = g_csr[e], s1 = g_csr[e + 1];
        float l0 = g_as[s0 * HEADS + hh] + dvh;
        float l1 = g_as[s1 * HEADS + hh] + dvh;
        l0 = fmaxf(l0, 0.2f * l0);
        l1 = fmaxf(l1, 0.2f * l1);
        float w0 = __expf(l0), w1 = __expf(l1);
        uint4 v0 = *((const uint4*)(hsrc + (long)s0 * HC) + lane);
        uint4 v1 = *((const uint4*)(hsrc + (long)s1 * HC) + lane);
        fma8(a, w0, v0);
        fma8(a, w1, v1);
    }
    if (e < end) {
        int s0 = g_csr[e];
        float l0 = g_as[s0 * HEADS + hh] + dvh;
        l0 = fmaxf(l0, 0.2f * l0);
        uint4 v0 = *((const uint4*)(hsrc + (long)s0 * HC) + lane);
        fma8(a, __expf(l0), v0);
    }
    #pragma unroll
    for (int j = 0; j < 8; j++) a[j] *= invh;
    if (!meanHeads) {
        float4* op = (float4*)(outp + (long)d * HC) + lane * 2;
        op[0] = make_float4(a[0], a[1], a[2], a[3]);
        op[1] = make_float4(a[4], a[5], a[6], a[7]);
    } else {
        // mean over heads: lanes L, L^8, L^16, L^24 hold same local channels
        #pragma unroll
        for (int j = 0; j < 8; j++) {
            a[j] += __shfl_xor_sync(0xffffffffu, a[j], 8);
            a[j] += __shfl_xor_sync(0xffffffffu, a[j], 16);
        }
        if (lane < 8) {
            float4* op = (float4*)(outp + (long)d * HID) + lane * 2;
            op[0] = make_float4(0.25f * a[0], 0.25f * a[1], 0.25f * a[2], 0.25f * a[3]);
            op[1] = make_float4(0.25f * a[4], 0.25f * a[5], 0.25f * a[6], 0.25f * a[7]);
        }
    }
}

__global__ void bn_stats(const float* __restrict__ x, int N, int C) {
    int tid = threadIdx.x;
    int c = tid % C;
    int g = tid / C;
    int G = blockDim.x / C;
    int rows_per_block = (N + gridDim.x - 1) / gridDim.x;
    int r0 = blockIdx.x * rows_per_block;
    int r1 = min(N, r0 + rows_per_block);
    float s = 0.f, q = 0.f;
    for (int r = r0 + g; r < r1; r += G) {
        float v = x[(long)r * C + c];
        s += v;
        q += v * v;
    }
    __shared__ float sh[512];
    sh[tid] = s;
    sh[256 + tid] = q;
    __syncthreads();
    if (g == 0) {
        for (int gg = 1; gg < G; gg++) {
            s += sh[gg * C + c];
            q += sh[256 + gg * C + c];
        }
        atomicAdd(&g_stats[c], s);
        atomicAdd(&g_stats[C + c], q);
    }
}

__global__ void bn_finalize(const float* __restrict__ gamma,
                            const float* __restrict__ beta, int N, int C) {
    int c = threadIdx.x;
    if (c >= C) return;
    float invN = 1.f / (float)N;
    float mean = g_stats[c] * invN;
    float var = g_stats[C + c] * invN - mean * mean;
    float sc = gamma[c] * rsqrtf(var + 1e-5f);
    g_scale[c] = sc;
    g_shift[c] = beta[c] - mean * sc;
}

__global__ void bn_apply_elu(float* __restrict__ x, const float* __restrict__ gamma,
                             const float* __restrict__ beta, int N, int C) {
    int i = blockIdx.x * blockDim.x + threadIdx.x;
    if (i >= N * C) return;
    int c = i % C;
    float invN = 1.f / (float)N;
    float mean = g_stats[c] * invN;
    float var = g_stats[C + c] * invN - mean * mean;
    float inv = rsqrtf(var + 1e-5f);
    float v = (x[i] - mean) * inv * gamma[c] + beta[c];
    v = (v > 0.f) ? v : expm1f(v);
    x[i] = v;
}

__global__ void fc_out(const float* __restrict__ W, const float* __restrict__ b,
                       float* __restrict__ out) {
    __shared__ float sW[HID * OUTD];
    for (int l = threadIdx.x; l < HID * OUTD; l += blockDim.x)
        sW[l] = W[l];
    __syncthreads();
    int i = blockIdx.x * blockDim.x + threadIdx.x;
    if (i >= NN * OUTD) return;
    int n = i / OUTD, o = i - n * OUTD;
    const float4* y4 = (const float4*)(g_y + (long)n * HID);
    float acc = b[o];
    #pragma unroll
    for (int k = 0; k < 16; k++) {
        float4 v = y4[k];
        acc += v.x * sW[(4 * k) * OUTD + o];
        acc += v.y * sW[(4 * k + 1) * OUTD + o];
        acc += v.z * sW[(4 * k + 2) * OUTD + o];
        acc += v.w * sW[(4 * k + 3) * OUTD + o];
    }
    out[i] = acc;
}

extern "C" void kernel_launch(void* const* d_in, const int* in_sizes, int n_in,
                              void* d_out, int out_size) {
    const float* x   = (const float*)d_in[0];
    const void*  ei  = d_in[1];
    const float* W1  = (const float*)d_in[2];
    const float* as1 = (const float*)d_in[3];
    const float* ad1 = (const float*)d_in[4];
    const float* W2  = (const float*)d_in[6];
    const float* as2 = (const float*)d_in[7];
    const float* ad2 = (const float*)d_in[8];
    const float* g1  = (const float*)d_in[10];
    const float* be1 = (const float*)d_in[11];
    const float* g2  = (const float*)d_in[12];
    const float* be2 = (const float*)d_in[13];
    const float* pw  = (const float*)d_in[14];
    const float* fcW = (const float*)d_in[15];
    const float* fcb = (const float*)d_in[16];
    float* out = (float*)d_out;

    __half* p_h;
    float *p_agg, *p_y, *p_scale, *p_shift;
    cudaGetSymbolAddress((void**)&p_h, g_h);
    cudaGetSymbolAddress((void**)&p_agg, g_agg);
    cudaGetSymbolAddress((void**)&p_y, g_y);
    cudaGetSymbolAddress((void**)&p_scale, g_scale);
    cudaGetSymbolAddress((void**)&p_shift, g_shift);

    static cudaStream_t s2 = nullptr;
    static cudaEvent_t evFork = nullptr, evJoin = nullptr;
    static int init_done = 0;
    if (!init_done) {
        cudaFuncSetAttribute(gemm_tf32, cudaFuncAttributeMaxDynamicSharedMemorySize,
                             GEMM_SMEM);
        cudaStreamCreateWithFlags(&s2, cudaStreamNonBlocking);
        cudaEventCreateWithFlags(&evFork, cudaEventDisableTiming);
        cudaEventCreateWithFlags(&evJoin, cudaEventDisableTiming);
        init_done = 1;
    }

    dim3 gemmGrid(HC / BNT, (NN + BM - 1) / BM);   // (2, 391)
    int edgeBlocks = (E2 + 255) / 256;
    int aggBlocks  = (NN * 32 + 255) / 256;

    // ---- fork: CSR build on side stream, concurrent with layer-1 GEMM ----
    cudaEventRecord(evFork, 0);
    cudaStreamWaitEvent(s2, evFork, 0);
    detect_dtype<<<1, 256, 0, s2>>>((const int*)ei);
    convert_hist<<<edgeBlocks, 256, 0, s2>>>(ei);
    alloc_off<<<(NN + 255) / 256, 256, 0, s2>>>();
    scatter_csr<<<edgeBlocks, 256, 0, s2>>>();
    cudaEventRecord(evJoin, s2);

    // ---- layer 1 GEMM (main stream, independent of CSR) ----
    gemm_tf32<<<gemmGrid, 256, GEMM_SMEM>>>(x, W1, p_h, as1, ad1, NN,
                                            nullptr, nullptr, nullptr);

    // ---- join: aggregation needs both ----
    cudaStreamWaitEvent(0, evJoin, 0);
    agg_csr<<<aggBlocks, 256>>>(p_h, p_agg, 0);
    bn_stats<<<512, 256>>>(p_agg, NN, HC);
    bn_finalize<<<1, 256>>>(g1, be1, NN, HC);

    // ---- layer 2 (BN1 affine + PReLU fused into A-load; head-mean fused into agg) ----
    gemm_tf32<<<gemmGrid, 256, GEMM_SMEM>>>(p_agg, W2, p_h, as2, ad2, NN,
                                            p_scale, p_shift, pw);
    agg_csr<<<aggBlocks, 256>>>(p_h, p_y, 1);
    bn_stats<<<512, 256>>>(p_y, NN, HID);
    bn_apply_elu<<<(NN * HID + 255) / 256, 256>>>(p_y, g2, be2, NN, HID);
    fc_out<<<(NN * OUTD + 255) / 256, 256>>>(fcW, fcb, out);
}

// round 12
// speedup vs baseline: 1.6114x; 1.0054x over previous
#include <cuda_runtime.h>
#include <cuda_fp16.h>

#define NN 50000
#define EE 800000
#define E2 850000      // EE + NN self loops
#define HC 256
#define HEADS 4
#define HID 64
#define OUTD 86
#define NBUCK 16

// GEMM tiling: 128x128 block tile (2 heads), 8 warps of 32x64
#define BM 128
#define BNT 128
#define BK 32
#define ASTRIDE 36
#define BSTRIDE 136
#define ASZ (BM * ASTRIDE)
#define BSZ (BK * BSTRIDE)
#define GEMM_SMEM ((2 * ASZ + 2 * BSZ) * 4)

// ---- scratch (device globals: allocation-free) ----
__device__ __half g_h[NN * HC];         // post-GEMM features, fp16
__device__ float g_agg[NN * HC];
__device__ float g_as[NN * HEADS];
__device__ float g_ad[NN * HEADS];
__device__ float g_y[NN * HID];
__device__ float g_statsB[NBUCK][512];  // bucketed BN partial sums (sum | sumsq)
__device__ float g_scale[HC];
__device__ float g_shift[HC];
__device__ float g_scale2[HID];
__device__ float g_shift2[HID];
__device__ int   g_src[E2];
__device__ int   g_dst[E2];
__device__ int   g_rank[E2];
__device__ int   g_deg[NN];
__device__ int   g_off[NN];
__device__ int   g_cursor;
__device__ int   g_csr[E2];
__device__ int   g_is64;

// ---------------- dtype probe + zero degree array + buckets (single block) ----------------
__global__ void detect_dtype(const int* __restrict__ ei32) {
    __shared__ int any;
    int t = threadIdx.x;
    if (t == 0) { any = 0; g_cursor = 0; }
    __syncthreads();
    if (ei32[2 * t + 1] != 0) any = 1;
    for (int i = t; i < NN; i += 256) g_deg[i] = 0;
    float* sb = &g_statsB[0][0];
    for (int i = t; i < NBUCK * 512; i += 256) sb[i] = 0.f;
    __syncthreads();
    if (t == 0) g_is64 = !any;
}

// ---------------- normalize edge index + self loops + degree histogram ----------------
__global__ void convert_hist(const void* __restrict__ eiv) {
    int e = blockIdx.x * blockDim.x + threadIdx.x;
    if (e >= E2) return;
    int s, d;
    if (e >= EE) {
        s = d = e - EE;
    } else if (g_is64) {
        const long long* p = (const long long*)eiv;
        s = (int)p[e];
        d = (int)p[EE + e];
    } else {
        const int* p = (const int*)eiv;
        s = p[e];
        d = p[EE + e];
    }
    g_src[e] = s;
    g_dst[e] = d;
    g_rank[e] = atomicAdd(&g_deg[d], 1);
}

// ---------------- bump-allocator offsets (no scan needed) ----------------
__global__ void alloc_off() {
    int n = blockIdx.x * blockDim.x + threadIdx.x;
    if (n >= NN) return;
    g_off[n] = atomicAdd(&g_cursor, g_deg[n]);
}

__global__ void scatter_csr() {
    int e = blockIdx.x * blockDim.x + threadIdx.x;
    if (e >= E2) return;
    g_csr[g_off[g_dst[e]] + g_rank[e]] = g_src[e];
}

// ---------------- TF32 GEMM 128x128 + fused BN/PReLU pre-op + attn epilogue ----------------
__device__ __forceinline__ unsigned f2tf(float x) {
    unsigned r;
    asm("cvt.rna.tf32.f32 %0, %1;" : "=r"(r) : "f"(x));
    return r;
}

__global__ __launch_bounds__(256) void gemm_tf32(
        const float* __restrict__ A, const float* __restrict__ B,
        __half* __restrict__ C, const float* __restrict__ attS,
        const float* __restrict__ attD, int M,
        const float* __restrict__ scale, const float* __restrict__ shift,
        const float* __restrict__ pw) {
    extern __shared__ float sm[];
    float* sA = sm;
    float* sB = sm + 2 * ASZ;
    const int K = 256;
    int tid = threadIdx.x, lane = tid & 31, warp = tid >> 5;
    int wm = warp >> 1, wn = warp & 1;   // 4x2 warps, 32x64 per warp
    int g = lane >> 2, tg = lane & 3;
    int rowBase = blockIdx.y * BM;
    int colBase = blockIdx.x * BNT;
    int head = blockIdx.x * 2 + wn;      // each warp owns a full head
    float w = scale ? pw[0] : 0.f;

    float acc[2][8][4];
    #pragma unroll
    for (int mt = 0; mt < 2; mt++)
        #pragma unroll
        for (int nt = 0; nt < 8; nt++)
            #pragma unroll
            for (int i = 0; i < 4; i++) acc[mt][nt][i] = 0.f;

    float4 av[4], bv[4];
    auto loadA = [&](int k0) {
        #pragma unroll
        for (int i = 0; i < 4; i++) {
            int F = tid + i * 256;
            int r = rowBase + (F >> 3);
            int c = (F & 7) * 4;
            if (r < M) {
                float4 v = *(const float4*)(A + (long)r * K + k0 + c);
                if (scale) {
                    float4 sc = *(const float4*)(scale + k0 + c);
                    float4 sh = *(const float4*)(shift + k0 + c);
                    v.x = fmaf(v.x, sc.x, sh.x); v.x = (v.x >= 0.f) ? v.x : w * v.x;
                    v.y = fmaf(v.y, sc.y, sh.y); v.y = (v.y >= 0.f) ? v.y : w * v.y;
                    v.z = fmaf(v.z, sc.z, sh.z); v.z = (v.z >= 0.f) ? v.z : w * v.z;
                    v.w = fmaf(v.w, sc.w, sh.w); v.w = (v.w >= 0.f) ? v.w : w * v.w;
                }
                av[i] = v;
            } else {
                av[i] = make_float4(0.f, 0.f, 0.f, 0.f);
            }
        }
        #pragma unroll
        for (int i = 0; i < 4; i++) {
            int F = tid + i * 256;
            int r = k0 + (F >> 5);
            int c = colBase + (F & 31) * 4;
            bv[i] = *(const float4*)(B + (long)r * HC + c);
        }
    };
    auto storeT = [&](int buf) {
        float* pA = sA + buf * ASZ;
        #pragma unroll
        for (int i = 0; i < 4; i++) {
            int F = tid + i * 256;
            int r = F >> 3, c = (F & 7) * 4;
            float4 v;
            v.x = __uint_as_float(f2tf(av[i].x));
            v.y = __uint_as_float(f2tf(av[i].y));
            v.z = __uint_as_float(f2tf(av[i].z));
            v.w = __uint_as_float(f2tf(av[i].w));
            *(float4*)(pA + r * ASTRIDE + c) = v;
        }
        float* pB = sB + buf * BSZ;
        #pragma unroll
        for (int i = 0; i < 4; i++) {
            int F = tid + i * 256;
            int r = F >> 5, c = (F & 31) * 4;
            float4 v;
            v.x = __uint_as_float(f2tf(bv[i].x));
            v.y = __uint_as_float(f2tf(bv[i].y));
            v.z = __uint_as_float(f2tf(bv[i].z));
            v.w = __uint_as_float(f2tf(bv[i].w));
            *(float4*)(pB + r * BSTRIDE + c) = v;
        }
    };

    loadA(0);
    storeT(0);
    __syncthreads();

    const int iters = K / BK;
    for (int it = 0; it < iters; it++) {
        int buf = it & 1;
        if (it + 1 < iters) loadA((it + 1) * BK);
        const float* pA = sA + buf * ASZ;
        const float* pB = sB + buf * BSZ;
        #pragma unroll
        for (int ks = 0; ks < 4; ks++) {
            int k = ks * 8;
            unsigned a[2][4], b[8][2];
            #pragma unroll
            for (int mt = 0; mt < 2; mt++) {
                int r0 = wm * 32 + mt * 16;
                a[mt][0] = __float_as_uint(pA[(r0 + g) * ASTRIDE + k + tg]);
                a[mt][1] = __float_as_uint(pA[(r0 + g + 8) * ASTRIDE + k + tg]);
                a[mt][2] = __float_as_uint(pA[(r0 + g) * ASTRIDE + k + tg + 4]);
                a[mt][3] = __float_as_uint(pA[(r0 + g + 8) * ASTRIDE + k + tg + 4]);
            }
            #pragma unroll
            for (int nt = 0; nt < 8; nt++) {
                int c0 = wn * 64 + nt * 8;
                b[nt][0] = __float_as_uint(pB[(k + tg) * BSTRIDE + c0 + g]);
                b[nt][1] = __float_as_uint(pB[(k + tg + 4) * BSTRIDE + c0 + g]);
            }
            #pragma unroll
            for (int mt = 0; mt < 2; mt++)
                #pragma unroll
                for (int nt = 0; nt < 8; nt++) {
                    asm volatile(
                        "mma.sync.aligned.m16n8k8.row.col.f32.tf32.tf32.f32 "
                        "{%0,%1,%2,%3}, {%4,%5,%6,%7}, {%8,%9}, {%0,%1,%2,%3};"
                        : "+f"(acc[mt][nt][0]), "+f"(acc[mt][nt][1]),
                          "+f"(acc[mt][nt][2]), "+f"(acc[mt][nt][3])
                        : "r"(a[mt][0]), "r"(a[mt][1]), "r"(a[mt][2]), "r"(a[mt][3]),
                          "r"(b[nt][0]), "r"(b[nt][1]));
                }
        }
        if (it + 1 < iters) storeT(buf ^ 1);
        __syncthreads();
    }

    // ---- C store (fp16) ----
    #pragma unroll
    for (int mt = 0; mt < 2; mt++) {
        int r = rowBase + wm * 32 + mt * 16 + g;
        #pragma unroll
        for (int nt = 0; nt < 8; nt++) {
            int c = colBase + wn * 64 + nt * 8 + tg * 2;
            if (r < M)
                *(__half2*)(C + (long)r * HC + c) =
                    __floats2half2_rn(acc[mt][nt][0], acc[mt][nt][1]);
            if (r + 8 < M)
                *(__half2*)(C + (long)(r + 8) * HC + c) =
                    __floats2half2_rn(acc[mt][nt][2], acc[mt][nt][3]);
        }
    }

    // ---- fused attention scores: warp-local (each warp owns one head) ----
    float ps0[2] = {0.f, 0.f}, ps1[2] = {0.f, 0.f};
    float pd0[2] = {0.f, 0.f}, pd1[2] = {0.f, 0.f};
    #pragma unroll
    for (int nt = 0; nt < 8; nt++) {
        int lc = nt * 8 + tg * 2;         // column within head
        float s0 = attS[head * HID + lc], s1 = attS[head * HID + lc + 1];
        float d0 = attD[head * HID + lc], d1 = attD[head * HID + lc + 1];
        #pragma unroll
        for (int mt = 0; mt < 2; mt++) {
            ps0[mt] += acc[mt][nt][0] * s0 + acc[mt][nt][1] * s1;
            ps1[mt] += acc[mt][nt][2] * s0 + acc[mt][nt][3] * s1;
            pd0[mt] += acc[mt][nt][0] * d0 + acc[mt][nt][1] * d1;
            pd1[mt] += acc[mt][nt][2] * d0 + acc[mt][nt][3] * d1;
        }
    }
    #pragma unroll
    for (int o = 1; o <= 2; o <<= 1) {
        #pragma unroll
        for (int mt = 0; mt < 2; mt++) {
            ps0[mt] += __shfl_xor_sync(0xffffffffu, ps0[mt], o);
            ps1[mt] += __shfl_xor_sync(0xffffffffu, ps1[mt], o);
            pd0[mt] += __shfl_xor_sync(0xffffffffu, pd0[mt], o);
            pd1[mt] += __shfl_xor_sync(0xffffffffu, pd1[mt], o);
        }
    }
    if (tg == 0) {
        #pragma unroll
        for (int mt = 0; mt < 2; mt++) {
            int r = rowBase + wm * 32 + mt * 16 + g;
            if (r < M) {
                g_as[r * HEADS + head] = ps0[mt];
                g_ad[r * HEADS + head] = pd0[mt];
            }
            if (r + 8 < M) {
                g_as[(r + 8) * HEADS + head] = ps1[mt];
                g_ad[(r + 8) * HEADS + head] = pd1[mt];
            }
        }
    }
}

// ---------------- CSR aggregation: warp per dst node + fused BN stats ----------------
__device__ __forceinline__ void fma8(float* a, float al, uint4 v) {
    float2 f0 = __half22float2(*(__half2*)&v.x);
    float2 f1 = __half22float2(*(__half2*)&v.y);
    float2 f2 = __half22float2(*(__half2*)&v.z);
    float2 f3 = __half22float2(*(__half2*)&v.w);
    a[0] = fmaf(al, f0.x, a[0]); a[1] = fmaf(al, f0.y, a[1]);
    a[2] = fmaf(al, f1.x, a[2]); a[3] = fmaf(al, f1.y, a[3]);
    a[4] = fmaf(al, f2.x, a[4]); a[5] = fmaf(al, f2.y, a[5]);
    a[6] = fmaf(al, f3.x, a[6]); a[7] = fmaf(al, f3.y, a[7]);
}

// grid MUST be exactly NN*32/256 = 6250 blocks (all warps map to a valid node)
__global__ __launch_bounds__(256) void agg_csr(const __half* __restrict__ hsrc,
                                               float* __restrict__ outp,
                                               int meanHeads) {
    __shared__ float sV[8][256];
    int tid = threadIdx.x;
    int warp = tid >> 5;
    int lane = tid & 31;
    int d = (blockIdx.x * blockDim.x + tid) >> 5;
    int start = g_off[d], end = start + g_deg[d];
    float4 dv = *(const float4*)(g_ad + d * HEADS);
    float d0 = 0.f, d1 = 0.f, d2 = 0.f, d3 = 0.f;
    // pass 1: softmax denominator (warp-parallel over edges)
    for (int e = start + lane; e < end; e += 32) {
        int s = g_csr[e];
        float4 sv = *(const float4*)(g_as + s * HEADS);
        float l0 = sv.x + dv.x; l0 = fmaxf(l0, 0.2f * l0); d0 += __expf(l0);
        float l1 = sv.y + dv.y; l1 = fmaxf(l1, 0.2f * l1); d1 += __expf(l1);
        float l2 = sv.z + dv.z; l2 = fmaxf(l2, 0.2f * l2); d2 += __expf(l2);
        float l3 = sv.w + dv.w; l3 = fmaxf(l3, 0.2f * l3); d3 += __expf(l3);
    }
    #pragma unroll
    for (int o = 16; o > 0; o >>= 1) {
        d0 += __shfl_xor_sync(0xffffffffu, d0, o);
        d1 += __shfl_xor_sync(0xffffffffu, d1, o);
        d2 += __shfl_xor_sync(0xffffffffu, d2, o);
        d3 += __shfl_xor_sync(0xffffffffu, d3, o);
    }
    int hh = lane >> 3;            // lane covers channels [lane*8, lane*8+8)
    float dvh = (hh == 0) ? dv.x : (hh == 1) ? dv.y : (hh == 2) ? dv.z : dv.w;
    float den = (hh == 0) ? d0 : (hh == 1) ? d1 : (hh == 2) ? d2 : d3;
    float invh = 1.f / (den + 1e-16f);
    // pass 2: weighted gather (exp recomputed per lane), unroll 2
    float a[8] = {0.f, 0.f, 0.f, 0.f, 0.f, 0.f, 0.f, 0.f};
    int e = start;
    for (; e + 2 <= end; e += 2) {
        int s0 = g_csr[e], s1 = g_csr[e + 1];
        float l0 = g_as[s0 * HEADS + hh] + dvh;
        float l1 = g_as[s1 * HEADS + hh] + dvh;
        l0 = fmaxf(l0, 0.2f * l0);
        l1 = fmaxf(l1, 0.2f * l1);
        float w0 = __expf(l0), w1 = __expf(l1);
        uint4 v0 = *((const uint4*)(hsrc + (long)s0 * HC) + lane);
        uint4 v1 = *((const uint4*)(hsrc + (long)s1 * HC) + lane);
        fma8(a, w0, v0);
        fma8(a, w1, v1);
    }
    if (e < end) {
        int s0 = g_csr[e];
        float l0 = g_as[s0 * HEADS + hh] + dvh;
        l0 = fmaxf(l0, 0.2f * l0);
        uint4 v0 = *((const uint4*)(hsrc + (long)s0 * HC) + lane);
        fma8(a, __expf(l0), v0);
    }
    #pragma unroll
    for (int j = 0; j < 8; j++) a[j] *= invh;
    int bkt = blockIdx.x & (NBUCK - 1);
    if (!meanHeads) {
        float4* op = (float4*)(outp + (long)d * HC) + lane * 2;
        op[0] = make_float4(a[0], a[1], a[2], a[3]);
        op[1] = make_float4(a[4], a[5], a[6], a[7]);
        #pragma unroll
        for (int j = 0; j < 8; j++) sV[warp][lane * 8 + j] = a[j];
        __syncthreads();
        int c = tid;   // 0..255
        float s = 0.f, q = 0.f;
        #pragma unroll
        for (int w = 0; w < 8; w++) {
            float v = sV[w][c];
            s += v;
            q += v * v;
        }
        atomicAdd(&g_statsB[bkt][c], s);
        atomicAdd(&g_statsB[bkt][256 + c], q);
    } else {
        // mean over heads: lanes L, L^8, L^16, L^24 hold same local channels
        #pragma unroll
        for (int j = 0; j < 8; j++) {
            a[j] += __shfl_xor_sync(0xffffffffu, a[j], 8);
            a[j] += __shfl_xor_sync(0xffffffffu, a[j], 16);
            a[j] *= 0.25f;
        }
        if (lane < 8) {
            float4* op = (float4*)(outp + (long)d * HID) + lane * 2;
            op[0] = make_float4(a[0], a[1], a[2], a[3]);
            op[1] = make_float4(a[4], a[5], a[6], a[7]);
            #pragma unroll
            for (int j = 0; j < 8; j++) sV[warp][lane * 8 + j] = a[j];
        }
        __syncthreads();
        if (tid < HID) {
            int c = tid;   // 0..63
            float s = 0.f, q = 0.f;
            #pragma unroll
            for (int w = 0; w < 8; w++) {
                float v = sV[w][c];
                s += v;
                q += v * v;
            }
            atomicAdd(&g_statsB[bkt][c], s);
            atomicAdd(&g_statsB[bkt][256 + c], q);
        }
    }
}

// ---------------- layer-1 BN affine from bucketed stats; re-zero buckets ----------------
__global__ void bn_finalize(const float* __restrict__ gamma,
                            const float* __restrict__ beta) {
    int c = threadIdx.x;   // 0..255
    float s = 0.f, q = 0.f;
    #pragma unroll
    for (int b = 0; b < NBUCK; b++) {
        s += g_statsB[b][c];
        q += g_statsB[b][256 + c];
    }
    float invN = 1.f / (float)NN;
    float mean = s * invN;
    float var = q * invN - mean * mean;
    float sc = gamma[c] * rsqrtf(var + 1e-5f);
    g_scale[c] = sc;
    g_shift[c] = beta[c] - mean * sc;
    #pragma unroll
    for (int b = 0; b < NBUCK; b++) {
        g_statsB[b][c] = 0.f;
        g_statsB[b][256 + c] = 0.f;
    }
}

// ---------------- layer-2 BN affine (y path, 64 channels) ----------------
__global__ void bn_finalize2(const float* __restrict__ gamma,
                             const float* __restrict__ beta) {
    int c = threadIdx.x;
    if (c >= HID) return;
    float s = 0.f, q = 0.f;
    #pragma unroll
    for (int b = 0; b < NBUCK; b++) {
        s += g_statsB[b][c];
        q += g_statsB[b][256 + c];
    }
    float invN = 1.f / (float)NN;
    float mean = s * invN;
    float var = q * invN - mean * mean;
    float sc = gamma[c] * rsqrtf(var + 1e-5f);
    g_scale2[c] = sc;
    g_shift2[c] = beta[c] - mean * sc;
}

__global__ void bn_apply_elu(float* __restrict__ x) {
    int i = blockIdx.x * blockDim.x + threadIdx.x;
    if (i >= NN * HID) return;
    int c = i & (HID - 1);
    float v = x[i] * g_scale2[c] + g_shift2[c];
    v = (v > 0.f) ? v : expm1f(v);
    x[i] = v;
}

__global__ void fc_out(const float* __restrict__ W, const float* __restrict__ b,
                       float* __restrict__ out) {
    __shared__ float sW[HID * OUTD];
    for (int l = threadIdx.x; l < HID * OUTD; l += blockDim.x)
        sW[l] = W[l];
    __syncthreads();
    int i = blockIdx.x * blockDim.x + threadIdx.x;
    if (i >= NN * OUTD) return;
    int n = i / OUTD, o = i - n * OUTD;
    const float4* y4 = (const float4*)(g_y + (long)n * HID);
    float acc = b[o];
    #pragma unroll
    for (int k = 0; k < 16; k++) {
        float4 v = y4[k];
        acc += v.x * sW[(4 * k) * OUTD + o];
        acc += v.y * sW[(4 * k + 1) * OUTD + o];
        acc += v.z * sW[(4 * k + 2) * OUTD + o];
        acc += v.w * sW[(4 * k + 3) * OUTD + o];
    }
    out[i] = acc;
}

extern "C" void kernel_launch(void* const* d_in, const int* in_sizes, int n_in,
                              void* d_out, int out_size) {
    const float* x   = (const float*)d_in[0];
    const void*  ei  = d_in[1];
    const float* W1  = (const float*)d_in[2];
    const float* as1 = (const float*)d_in[3];
    const float* ad1 = (const float*)d_in[4];
    const float* W2  = (const float*)d_in[6];
    const float* as2 = (const float*)d_in[7];
    const float* ad2 = (const float*)d_in[8];
    const float* g1  = (const float*)d_in[10];
    const float* be1 = (const float*)d_in[11];
    const float* g2  = (const float*)d_in[12];
    const float* be2 = (const float*)d_in[13];
    const float* pw  = (const float*)d_in[14];
    const float* fcW = (const float*)d_in[15];
    const float* fcb = (const float*)d_in[16];
    float* out = (float*)d_out;

    __half* p_h;
    float *p_agg, *p_y, *p_scale, *p_shift;
    cudaGetSymbolAddress((void**)&p_h, g_h);
    cudaGetSymbolAddress((void**)&p_agg, g_agg);
    cudaGetSymbolAddress((void**)&p_y, g_y);
    cudaGetSymbolAddress((void**)&p_scale, g_scale);
    cudaGetSymbolAddress((void**)&p_shift, g_shift);

    static cudaStream_t s2 = nullptr;
    static cudaEvent_t evFork = nullptr, evJoin = nullptr;
    static int init_done = 0;
    if (!init_done) {
        cudaFuncSetAttribute(gemm_tf32, cudaFuncAttributeMaxDynamicSharedMemorySize,
                             GEMM_SMEM);
        cudaStreamCreateWithFlags(&s2, cudaStreamNonBlocking);
        cudaEventCreateWithFlags(&evFork, cudaEventDisableTiming);
        cudaEventCreateWithFlags(&evJoin, cudaEventDisableTiming);
        init_done = 1;
    }

    dim3 gemmGrid(HC / BNT, (NN + BM - 1) / BM);   // (2, 391)
    int edgeBlocks = (E2 + 255) / 256;
    int aggBlocks  = NN * 32 / 256;                 // 6250 exact

    // ---- fork: CSR build (+ bucket zeroing) on side stream, concurrent with GEMM1 ----
    cudaEventRecord(evFork, 0);
    cudaStreamWaitEvent(s2, evFork, 0);
    detect_dtype<<<1, 256, 0, s2>>>((const int*)ei);
    convert_hist<<<edgeBlocks, 256, 0, s2>>>(ei);
    alloc_off<<<(NN + 255) / 256, 256, 0, s2>>>();
    scatter_csr<<<edgeBlocks, 256, 0, s2>>>();
    cudaEventRecord(evJoin, s2);

    // ---- layer 1 GEMM (main stream, independent of CSR) ----
    gemm_tf32<<<gemmGrid, 256, GEMM_SMEM>>>(x, W1, p_h, as1, ad1, NN,
                                            nullptr, nullptr, nullptr);

    // ---- join: aggregation needs both; BN1 stats fused into agg ----
    cudaStreamWaitEvent(0, evJoin, 0);
    agg_csr<<<aggBlocks, 256>>>(p_h, p_agg, 0);
    bn_finalize<<<1, 256>>>(g1, be1);

    // ---- layer 2 (BN1 affine + PReLU fused into GEMM A-load; head-mean + BN2 stats fused into agg) ----
    gemm_tf32<<<gemmGrid, 256, GEMM_SMEM>>>(p_agg, W2, p_h, as2, ad2, NN,
                                            p_scale, p_shift, pw);
    agg_csr<<<aggBlocks, 256>>>(p_h, p_y, 1);
    bn_finalize2<<<1, 64>>>(g2, be2);
    bn_apply_elu<<<(NN * HID + 255) / 256, 256>>>(p_y);
    fc_out<<<(NN * OUTD + 255) / 256, 256>>>(fcW, fcb, out);
}

// round 13
// speedup vs baseline: 1.8513x; 1.1489x over previous
#include <cuda_runtime.h>
#include <cuda_fp16.h>

#define NN 50000
#define EE 800000
#define E2 850000      // EE + NN self loops
#define HC 256
#define HEADS 4
#define HID 64
#define OUTD 86
#define NBUCK 16

// GEMM tiling: 128x128 block tile (2 heads), 8 warps of 32x64
#define BM 128
#define BNT 128
#define BK 32
#define ASTRIDE 36
#define BSTRIDE 136
#define ASZ (BM * ASTRIDE)
#define BSZ (BK * BSTRIDE)
#define GEMM_SMEM ((2 * ASZ + 2 * BSZ) * 4)

// ---- scratch (device globals: allocation-free) ----
__device__ __half g_h[NN * HC];         // post-GEMM features, fp16
__device__ __half g_aggh[NN * HC];      // layer-1 aggregation output, fp16
__device__ float g_as[NN * HEADS];
__device__ float g_ad[NN * HEADS];
__device__ float g_y[NN * HID];
__device__ float g_statsB[NBUCK][512];  // bucketed BN partial sums (sum | sumsq)
__device__ float g_scale[HC];
__device__ float g_shift[HC];
__device__ float g_scale2[HID];
__device__ float g_shift2[HID];
__device__ int   g_src[E2];
__device__ int   g_dst[E2];
__device__ int   g_rank[E2];
__device__ int   g_deg[NN];
__device__ int   g_off[NN];
__device__ int   g_cursor;
__device__ int   g_csr[E2];
__device__ int   g_is64;

// ---------------- dtype probe + zero degree array + buckets (single block) ----------------
__global__ void detect_dtype(const int* __restrict__ ei32) {
    __shared__ int any;
    int t = threadIdx.x;
    if (t == 0) { any = 0; g_cursor = 0; }
    __syncthreads();
    if (ei32[2 * t + 1] != 0) any = 1;
    for (int i = t; i < NN; i += 256) g_deg[i] = 0;
    float* sb = &g_statsB[0][0];
    for (int i = t; i < NBUCK * 512; i += 256) sb[i] = 0.f;
    __syncthreads();
    if (t == 0) g_is64 = !any;
}

// ---------------- normalize edge index + self loops + degree histogram ----------------
__global__ void convert_hist(const void* __restrict__ eiv) {
    int e = blockIdx.x * blockDim.x + threadIdx.x;
    if (e >= E2) return;
    int s, d;
    if (e >= EE) {
        s = d = e - EE;
    } else if (g_is64) {
        const long long* p = (const long long*)eiv;
        s = (int)p[e];
        d = (int)p[EE + e];
    } else {
        const int* p = (const int*)eiv;
        s = p[e];
        d = p[EE + e];
    }
    g_src[e] = s;
    g_dst[e] = d;
    g_rank[e] = atomicAdd(&g_deg[d], 1);
}

// ---------------- bump-allocator offsets (no scan needed) ----------------
__global__ void alloc_off() {
    int n = blockIdx.x * blockDim.x + threadIdx.x;
    if (n >= NN) return;
    g_off[n] = atomicAdd(&g_cursor, g_deg[n]);
}

__global__ void scatter_csr() {
    int e = blockIdx.x * blockDim.x + threadIdx.x;
    if (e >= E2) return;
    g_csr[g_off[g_dst[e]] + g_rank[e]] = g_src[e];
}

// ---------------- TF32 GEMM 128x128 + fused BN/PReLU pre-op + attn epilogue ----------------
__device__ __forceinline__ unsigned f2tf(float x) {
    unsigned r;
    asm("cvt.rna.tf32.f32 %0, %1;" : "=r"(r) : "f"(x));
    return r;
}

__device__ __forceinline__ float4 loadA4(const float* p) {
    return *(const float4*)p;
}
__device__ __forceinline__ float4 loadA4(const __half* p) {
    uint2 u = *(const uint2*)p;
    float2 f0 = __half22float2(*(__half2*)&u.x);
    float2 f1 = __half22float2(*(__half2*)&u.y);
    return make_float4(f0.x, f0.y, f1.x, f1.y);
}

template <typename TA>
__global__ __launch_bounds__(256) void gemm_tf32(
        const TA* __restrict__ A, const float* __restrict__ B,
        __half* __restrict__ C, const float* __restrict__ attS,
        const float* __restrict__ attD, int M,
        const float* __restrict__ scale, const float* __restrict__ shift,
        const float* __restrict__ pw) {
    extern __shared__ float sm[];
    float* sA = sm;
    float* sB = sm + 2 * ASZ;
    const int K = 256;
    int tid = threadIdx.x, lane = tid & 31, warp = tid >> 5;
    int wm = warp >> 1, wn = warp & 1;   // 4x2 warps, 32x64 per warp
    int g = lane >> 2, tg = lane & 3;
    int rowBase = blockIdx.y * BM;
    int colBase = blockIdx.x * BNT;
    int head = blockIdx.x * 2 + wn;      // each warp owns a full head
    float w = scale ? pw[0] : 0.f;

    float acc[2][8][4];
    #pragma unroll
    for (int mt = 0; mt < 2; mt++)
        #pragma unroll
        for (int nt = 0; nt < 8; nt++)
            #pragma unroll
            for (int i = 0; i < 4; i++) acc[mt][nt][i] = 0.f;

    float4 av[4], bv[4];
    auto loadA = [&](int k0) {
        #pragma unroll
        for (int i = 0; i < 4; i++) {
            int F = tid + i * 256;
            int r = rowBase + (F >> 3);
            int c = (F & 7) * 4;
            if (r < M) {
                float4 v = loadA4(A + (long)r * K + k0 + c);
                if (scale) {
                    float4 sc = *(const float4*)(scale + k0 + c);
                    float4 sh = *(const float4*)(shift + k0 + c);
                    v.x = fmaf(v.x, sc.x, sh.x); v.x = (v.x >= 0.f) ? v.x : w * v.x;
                    v.y = fmaf(v.y, sc.y, sh.y); v.y = (v.y >= 0.f) ? v.y : w * v.y;
                    v.z = fmaf(v.z, sc.z, sh.z); v.z = (v.z >= 0.f) ? v.z : w * v.z;
                    v.w = fmaf(v.w, sc.w, sh.w); v.w = (v.w >= 0.f) ? v.w : w * v.w;
                }
                av[i] = v;
            } else {
                av[i] = make_float4(0.f, 0.f, 0.f, 0.f);
            }
        }
        #pragma unroll
        for (int i = 0; i < 4; i++) {
            int F = tid + i * 256;
            int r = k0 + (F >> 5);
            int c = colBase + (F & 31) * 4;
            bv[i] = *(const float4*)(B + (long)r * HC + c);
        }
    };
    auto storeT = [&](int buf) {
        float* pA = sA + buf * ASZ;
        #pragma unroll
        for (int i = 0; i < 4; i++) {
            int F = tid + i * 256;
            int r = F >> 3, c = (F & 7) * 4;
            float4 v;
            v.x = __uint_as_float(f2tf(av[i].x));
            v.y = __uint_as_float(f2tf(av[i].y));
            v.z = __uint_as_float(f2tf(av[i].z));
            v.w = __uint_as_float(f2tf(av[i].w));
            *(float4*)(pA + r * ASTRIDE + c) = v;
        }
        float* pB = sB + buf * BSZ;
        #pragma unroll
        for (int i = 0; i < 4; i++) {
            int F = tid + i * 256;
            int r = F >> 5, c = (F & 31) * 4;
            float4 v;
            v.x = __uint_as_float(f2tf(bv[i].x));
            v.y = __uint_as_float(f2tf(bv[i].y));
            v.z = __uint_as_float(f2tf(bv[i].z));
            v.w = __uint_as_float(f2tf(bv[i].w));
            *(float4*)(pB + r * BSTRIDE + c) = v;
        }
    };

    loadA(0);
    storeT(0);
    __syncthreads();

    const int iters = K / BK;
    for (int it = 0; it < iters; it++) {
        int buf = it & 1;
        if (it + 1 < iters) loadA((it + 1) * BK);
        const float* pA = sA + buf * ASZ;
        const float* pB = sB + buf * BSZ;
        #pragma unroll
        for (int ks = 0; ks < 4; ks++) {
            int k = ks * 8;
            unsigned a[2][4], b[8][2];
            #pragma unroll
            for (int mt = 0; mt < 2; mt++) {
                int r0 = wm * 32 + mt * 16;
                a[mt][0] = __float_as_uint(pA[(r0 + g) * ASTRIDE + k + tg]);
                a[mt][1] = __float_as_uint(pA[(r0 + g + 8) * ASTRIDE + k + tg]);
                a[mt][2] = __float_as_uint(pA[(r0 + g) * ASTRIDE + k + tg + 4]);
                a[mt][3] = __float_as_uint(pA[(r0 + g + 8) * ASTRIDE + k + tg + 4]);
            }
            #pragma unroll
            for (int nt = 0; nt < 8; nt++) {
                int c0 = wn * 64 + nt * 8;
                b[nt][0] = __float_as_uint(pB[(k + tg) * BSTRIDE + c0 + g]);
                b[nt][1] = __float_as_uint(pB[(k + tg + 4) * BSTRIDE + c0 + g]);
            }
            #pragma unroll
            for (int mt = 0; mt < 2; mt++)
                #pragma unroll
                for (int nt = 0; nt < 8; nt++) {
                    asm volatile(
                        "mma.sync.aligned.m16n8k8.row.col.f32.tf32.tf32.f32 "
                        "{%0,%1,%2,%3}, {%4,%5,%6,%7}, {%8,%9}, {%0,%1,%2,%3};"
                        : "+f"(acc[mt][nt][0]), "+f"(acc[mt][nt][1]),
                          "+f"(acc[mt][nt][2]), "+f"(acc[mt][nt][3])
                        : "r"(a[mt][0]), "r"(a[mt][1]), "r"(a[mt][2]), "r"(a[mt][3]),
                          "r"(b[nt][0]), "r"(b[nt][1]));
                }
        }
        if (it + 1 < iters) storeT(buf ^ 1);
        __syncthreads();
    }

    // ---- C store (fp16) ----
    #pragma unroll
    for (int mt = 0; mt < 2; mt++) {
        int r = rowBase + wm * 32 + mt * 16 + g;
        #pragma unroll
        for (int nt = 0; nt < 8; nt++) {
            int c = colBase + wn * 64 + nt * 8 + tg * 2;
            if (r < M)
                *(__half2*)(C + (long)r * HC + c) =
                    __floats2half2_rn(acc[mt][nt][0], acc[mt][nt][1]);
            if (r + 8 < M)
                *(__half2*)(C + (long)(r + 8) * HC + c) =
                    __floats2half2_rn(acc[mt][nt][2], acc[mt][nt][3]);
        }
    }

    // ---- fused attention scores: warp-local (each warp owns one head) ----
    float ps0[2] = {0.f, 0.f}, ps1[2] = {0.f, 0.f};
    float pd0[2] = {0.f, 0.f}, pd1[2] = {0.f, 0.f};
    #pragma unroll
    for (int nt = 0; nt < 8; nt++) {
        int lc = nt * 8 + tg * 2;         // column within head
        float s0 = attS[head * HID + lc], s1 = attS[head * HID + lc + 1];
        float d0 = attD[head * HID + lc], d1 = attD[head * HID + lc + 1];
        #pragma unroll
        for (int mt = 0; mt < 2; mt++) {
            ps0[mt] += acc[mt][nt][0] * s0 + acc[mt][nt][1] * s1;
            ps1[mt] += acc[mt][nt][2] * s0 + acc[mt][nt][3] * s1;
            pd0[mt] += acc[mt][nt][0] * d0 + acc[mt][nt][1] * d1;
            pd1[mt] += acc[mt][nt][2] * d0 + acc[mt][nt][3] * d1;
        }
    }
    #pragma unroll
    for (int o = 1; o <= 2; o <<= 1) {
        #pragma unroll
        for (int mt = 0; mt < 2; mt++) {
            ps0[mt] += __shfl_xor_sync(0xffffffffu, ps0[mt], o);
            ps1[mt] += __shfl_xor_sync(0xffffffffu, ps1[mt], o);
            pd0[mt] += __shfl_xor_sync(0xffffffffu, pd0[mt], o);
            pd1[mt] += __shfl_xor_sync(0xffffffffu, pd1[mt], o);
        }
    }
    if (tg == 0) {
        #pragma unroll
        for (int mt = 0; mt < 2; mt++) {
            int r = rowBase + wm * 32 + mt * 16 + g;
            if (r < M) {
                g_as[r * HEADS + head] = ps0[mt];
                g_ad[r * HEADS + head] = pd0[mt];
            }
            if (r + 8 < M) {
                g_as[(r + 8) * HEADS + head] = ps1[mt];
                g_ad[(r + 8) * HEADS + head] = pd1[mt];
            }
        }
    }
}

// ---------------- CSR aggregation: warp per dst node + fused BN stats ----------------
__device__ __forceinline__ void fma8(float* a, float al, uint4 v) {
    float2 f0 = __half22float2(*(__half2*)&v.x);
    float2 f1 = __half22float2(*(__half2*)&v.y);
    float2 f2 = __half22float2(*(__half2*)&v.z);
    float2 f3 = __half22float2(*(__half2*)&v.w);
    a[0] = fmaf(al, f0.x, a[0]); a[1] = fmaf(al, f0.y, a[1]);
    a[2] = fmaf(al, f1.x, a[2]); a[3] = fmaf(al, f1.y, a[3]);
    a[4] = fmaf(al, f2.x, a[4]); a[5] = fmaf(al, f2.y, a[5]);
    a[6] = fmaf(al, f3.x, a[6]); a[7] = fmaf(al, f3.y, a[7]);
}

// grid MUST be exactly NN*32/256 = 6250 blocks (all warps map to a valid node)
// meanHeads=0: outp16 = fp16 [NN,HC]; meanHeads=1: outp32 = fp32 [NN,HID]
__global__ __launch_bounds__(256) void agg_csr(const __half* __restrict__ hsrc,
                                               __half* __restrict__ outp16,
                                               float* __restrict__ outp32,
                                               int meanHeads) {
    __shared__ float sV[8][256];
    int tid = threadIdx.x;
    int warp = tid >> 5;
    int lane = tid & 31;
    int d = (blockIdx.x * blockDim.x + tid) >> 5;
    int start = g_off[d], end = start + g_deg[d];
    float4 dv = *(const float4*)(g_ad + d * HEADS);
    float d0 = 0.f, d1 = 0.f, d2 = 0.f, d3 = 0.f;
    // pass 1: softmax denominator (warp-parallel over edges)
    for (int e = start + lane; e < end; e += 32) {
        int s = g_csr[e];
        float4 sv = *(const float4*)(g_as + s * HEADS);
        float l0 = sv.x + dv.x; l0 = fmaxf(l0, 0.2f * l0); d0 += __expf(l0);
        float l1 = sv.y + dv.y; l1 = fmaxf(l1, 0.2f * l1); d1 += __expf(l1);
        float l2 = sv.z + dv.z; l2 = fmaxf(l2, 0.2f * l2); d2 += __expf(l2);
        float l3 = sv.w + dv.w; l3 = fmaxf(l3, 0.2f * l3); d3 += __expf(l3);
    }
    #pragma unroll
    for (int o = 16; o > 0; o >>= 1) {
        d0 += __shfl_xor_sync(0xffffffffu, d0, o);
        d1 += __shfl_xor_sync(0xffffffffu, d1, o);
        d2 += __shfl_xor_sync(0xffffffffu, d2, o);
        d3 += __shfl_xor_sync(0xffffffffu, d3, o);
    }
    int hh = lane >> 3;            // lane covers channels [lane*8, lane*8+8)
    float dvh = (hh == 0) ? dv.x : (hh == 1) ? dv.y : (hh == 2) ? dv.z : dv.w;
    float den = (hh == 0) ? d0 : (hh == 1) ? d1 : (hh == 2) ? d2 : d3;
    float invh = 1.f / (den + 1e-16f);
    // pass 2: weighted gather (exp recomputed per lane), unroll 2
    float a[8] = {0.f, 0.f, 0.f, 0.f, 0.f, 0.f, 0.f, 0.f};
    int e = start;
    for (; e + 2 <= end; e += 2) {
        int s0 = g_csr[e], s1 = g_csr[e + 1];
        float l0 = g_as[s0 * HEADS + hh] + dvh;
        float l1 = g_as[s1 * HEADS + hh] + dvh;
        l0 = fmaxf(l0, 0.2f * l0);
        l1 = fmaxf(l1, 0.2f * l1);
        float w0 = __expf(l0), w1 = __expf(l1);
        uint4 v0 = *((const uint4*)(hsrc + (long)s0 * HC) + lane);
        uint4 v1 = *((const uint4*)(hsrc + (long)s1 * HC) + lane);
        fma8(a, w0, v0);
        fma8(a, w1, v1);
    }
    if (e < end) {
        int s0 = g_csr[e];
        float l0 = g_as[s0 * HEADS + hh] + dvh;
        l0 = fmaxf(l0, 0.2f * l0);
        uint4 v0 = *((const uint4*)(hsrc + (long)s0 * HC) + lane);
        fma8(a, __expf(l0), v0);
    }
    #pragma unroll
    for (int j = 0; j < 8; j++) a[j] *= invh;
    int bkt = blockIdx.x & (NBUCK - 1);
    if (!meanHeads) {
        // fp16 output (layer-2 GEMM input), 16B per lane
        uint4 ov;
        *(__half2*)&ov.x = __floats2half2_rn(a[0], a[1]);
        *(__half2*)&ov.y = __floats2half2_rn(a[2], a[3]);
        *(__half2*)&ov.z = __floats2half2_rn(a[4], a[5]);
        *(__half2*)&ov.w = __floats2half2_rn(a[6], a[7]);
        *((uint4*)(outp16 + (long)d * HC) + lane) = ov;
        #pragma unroll
        for (int j = 0; j < 8; j++) sV[warp][lane * 8 + j] = a[j];
        __syncthreads();
        int c = tid;   // 0..255
        float s = 0.f, q = 0.f;
        #pragma unroll
        for (int w = 0; w < 8; w++) {
            float v = sV[w][c];
            s += v;
            q += v * v;
        }
        atomicAdd(&g_statsB[bkt][c], s);
        atomicAdd(&g_statsB[bkt][256 + c], q);
    } else {
        // mean over heads: lanes L, L^8, L^16, L^24 hold same local channels
        #pragma unroll
        for (int j = 0; j < 8; j++) {
            a[j] += __shfl_xor_sync(0xffffffffu, a[j], 8);
            a[j] += __shfl_xor_sync(0xffffffffu, a[j], 16);
            a[j] *= 0.25f;
        }
        if (lane < 8) {
            float4* op = (float4*)(outp32 + (long)d * HID) + lane * 2;
            op[0] = make_float4(a[0], a[1], a[2], a[3]);
            op[1] = make_float4(a[4], a[5], a[6], a[7]);
            #pragma unroll
            for (int j = 0; j < 8; j++) sV[warp][lane * 8 + j] = a[j];
        }
        __syncthreads();
        if (tid < HID) {
            int c = tid;   // 0..63
            float s = 0.f, q = 0.f;
            #pragma unroll
            for (int w = 0; w < 8; w++) {
                float v = sV[w][c];
                s += v;
                q += v * v;
            }
            atomicAdd(&g_statsB[bkt][c], s);
            atomicAdd(&g_statsB[bkt][256 + c], q);
        }
    }
}

// ---------------- layer-1 BN affine from bucketed stats; re-zero buckets ----------------
__global__ void bn_finalize(const float* __restrict__ gamma,
                            const float* __restrict__ beta) {
    int c = threadIdx.x;   // 0..255
    float s = 0.f, q = 0.f;
    #pragma unroll
    for (int b = 0; b < NBUCK; b++) {
        s += g_statsB[b][c];
        q += g_statsB[b][256 + c];
    }
    float invN = 1.f / (float)NN;
    float mean = s * invN;
    float var = q * invN - mean * mean;
    float sc = gamma[c] * rsqrtf(var + 1e-5f);
    g_scale[c] = sc;
    g_shift[c] = beta[c] - mean * sc;
    #pragma unroll
    for (int b = 0; b < NBUCK; b++) {
        g_statsB[b][c] = 0.f;
        g_statsB[b][256 + c] = 0.f;
    }
}

// ---------------- layer-2 BN affine (y path, 64 channels) ----------------
__global__ void bn_finalize2(const float* __restrict__ gamma,
                             const float* __restrict__ beta) {
    int c = threadIdx.x;
    if (c >= HID) return;
    float s = 0.f, q = 0.f;
    #pragma unroll
    for (int b = 0; b < NBUCK; b++) {
        s += g_statsB[b][c];
        q += g_statsB[b][256 + c];
    }
    float invN = 1.f / (float)NN;
    float mean = s * invN;
    float var = q * invN - mean * mean;
    float sc = gamma[c] * rsqrtf(var + 1e-5f);
    g_scale2[c] = sc;
    g_shift2[c] = beta[c] - mean * sc;
}

// ---------------- fused BN2-affine + ELU + final linear ----------------
// block handles 32 nodes: stage y tile (BN+ELU applied) in smem, then matmul
__global__ __launch_bounds__(256) void fc_fused(const float* __restrict__ W,
                                                const float* __restrict__ b,
                                                float* __restrict__ out) {
    __shared__ float sW[HID * OUTD];   // 21.5 KB
    __shared__ float sY[32 * HID];     // 8 KB
    int tid = threadIdx.x;
    for (int l = tid; l < HID * OUTD; l += 256)
        sW[l] = W[l];
    int n0 = blockIdx.x * 32;
    for (int i = tid; i < 32 * HID; i += 256) {
        int n = n0 + (i >> 6), c = i & (HID - 1);
        float v = 0.f;
        if (n < NN) {
            v = g_y[(long)n * HID + c] * g_scale2[c] + g_shift2[c];
            v = (v > 0.f) ? v : expm1f(v);
        }
        sY[i] = v;
    }
    __syncthreads();
    for (int j = tid; j < 32 * OUTD; j += 256) {
        int nl = j / OUTD, o = j - nl * OUTD;
        int n = n0 + nl;
        if (n >= NN) continue;
        const float* y = sY + nl * HID;
        float acc = b[o];
        #pragma unroll
        for (int k = 0; k < HID; k++)
            acc += y[k] * sW[k * OUTD + o];
        out[(long)n * OUTD + o] = acc;
    }
}

extern "C" void kernel_launch(void* const* d_in, const int* in_sizes, int n_in,
                              void* d_out, int out_size) {
    const float* x   = (const float*)d_in[0];
    const void*  ei  = d_in[1];
    const float* W1  = (const float*)d_in[2];
    const float* as1 = (const float*)d_in[3];
    const float* ad1 = (const float*)d_in[4];
    const float* W2  = (const float*)d_in[6];
    const float* as2 = (const float*)d_in[7];
    const float* ad2 = (const float*)d_in[8];
    const float* g1  = (const float*)d_in[10];
    const float* be1 = (const float*)d_in[11];
    const float* g2  = (const float*)d_in[12];
    const float* be2 = (const float*)d_in[13];
    const float* pw  = (const float*)d_in[14];
    const float* fcW = (const float*)d_in[15];
    const float* fcb = (const float*)d_in[16];
    float* out = (float*)d_out;

    __half *p_h, *p_aggh;
    float *p_y, *p_scale, *p_shift;
    cudaGetSymbolAddress((void**)&p_h, g_h);
    cudaGetSymbolAddress((void**)&p_aggh, g_aggh);
    cudaGetSymbolAddress((void**)&p_y, g_y);
    cudaGetSymbolAddress((void**)&p_scale, g_scale);
    cudaGetSymbolAddress((void**)&p_shift, g_shift);

    static cudaStream_t s2 = nullptr;
    static cudaEvent_t evFork = nullptr, evJoin = nullptr;
    static int init_done = 0;
    if (!init_done) {
        cudaFuncSetAttribute(gemm_tf32<float>,
                             cudaFuncAttributeMaxDynamicSharedMemorySize, GEMM_SMEM);
        cudaFuncSetAttribute(gemm_tf32<__half>,
                             cudaFuncAttributeMaxDynamicSharedMemorySize, GEMM_SMEM);
        cudaStreamCreateWithFlags(&s2, cudaStreamNonBlocking);
        cudaEventCreateWithFlags(&evFork, cudaEventDisableTiming);
        cudaEventCreateWithFlags(&evJoin, cudaEventDisableTiming);
        init_done = 1;
    }

    dim3 gemmGrid(HC / BNT, (NN + BM - 1) / BM);   // (2, 391)
    int edgeBlocks = (E2 + 255) / 256;
    int aggBlocks  = NN * 32 / 256;                 // 6250 exact

    // ---- fork: CSR build (+ bucket zeroing) on side stream, concurrent with GEMM1 ----
    cudaEventRecord(evFork, 0);
    cudaStreamWaitEvent(s2, evFork, 0);
    detect_dtype<<<1, 256, 0, s2>>>((const int*)ei);
    convert_hist<<<edgeBlocks, 256, 0, s2>>>(ei);
    alloc_off<<<(NN + 255) / 256, 256, 0, s2>>>();
    scatter_csr<<<edgeBlocks, 256, 0, s2>>>();
    cudaEventRecord(evJoin, s2);

    // ---- layer 1 GEMM (main stream, independent of CSR) ----
    gemm_tf32<float><<<gemmGrid, 256, GEMM_SMEM>>>(x, W1, p_h, as1, ad1, NN,
                                                   nullptr, nullptr, nullptr);

    // ---- join: aggregation needs both; BN1 stats fused into agg ----
    cudaStreamWaitEvent(0, evJoin, 0);
    agg_csr<<<aggBlocks, 256>>>(p_h, p_aggh, nullptr, 0);
    bn_finalize<<<1, 256>>>(g1, be1);

    // ---- layer 2 (BN1 affine + PReLU fused into GEMM A-load; head-mean + BN2 stats fused into agg) ----
    gemm_tf32<__half><<<gemmGrid, 256, GEMM_SMEM>>>(p_aggh, W2, p_h, as2, ad2, NN,
                                                    p_scale, p_shift, pw);
    agg_csr<<<aggBlocks, 256>>>(p_h, nullptr, p_y, 1);
    bn_finalize2<<<1, 64>>>(g2, be2);
    fc_fused<<<(NN + 31) / 32, 256>>>(fcW, fcb, out);
}

// round 14
// speedup vs baseline: 1.9513x; 1.0540x over previous
#include <cuda_runtime.h>
#include <cuda_fp16.h>

#define NN 50000
#define EE 800000
#define E2 850000      // EE + NN self loops
#define HC 256
#define HEADS 4
#define HID 64
#define OUTD 86
#define NBUCK 16
#define ECACHE 64      // per-warp cached edges in agg

// GEMM tiling: 128x128 block tile (2 heads), 8 warps of 32x64
#define BM 128
#define BNT 128
#define BK 32
#define ASTRIDE 36
#define BSTRIDE 136
#define ASZ (BM * ASTRIDE)
#define BSZ (BK * BSTRIDE)
#define GEMM_SMEM ((2 * ASZ + 2 * BSZ) * 4)

// ---- scratch (device globals: allocation-free) ----
__device__ __half g_h[NN * HC];         // post-GEMM features, fp16
__device__ __half g_aggh[NN * HC];      // layer-1 aggregation output, fp16
__device__ float g_as[NN * HEADS];
__device__ float g_ad[NN * HEADS];
__device__ float g_y[NN * HID];
__device__ float g_statsB[NBUCK][512];  // bucketed BN partial sums (sum | sumsq)
__device__ float g_scale[HC];
__device__ float g_shift[HC];
__device__ float g_scale2[HID];
__device__ float g_shift2[HID];
__device__ int   g_src[E2];
__device__ int   g_dst[E2];
__device__ int   g_rank[E2];
__device__ int   g_deg[NN];
__device__ int   g_off[NN];
__device__ int   g_cursor;
__device__ int   g_csr[E2];
__device__ int   g_is64;

// ---------------- dtype probe + zero degree array + buckets (single block) ----------------
__global__ void detect_dtype(const int* __restrict__ ei32) {
    __shared__ int any;
    int t = threadIdx.x;
    if (t == 0) { any = 0; g_cursor = 0; }
    __syncthreads();
    if (ei32[2 * t + 1] != 0) any = 1;
    for (int i = t; i < NN; i += 256) g_deg[i] = 0;
    float* sb = &g_statsB[0][0];
    for (int i = t; i < NBUCK * 512; i += 256) sb[i] = 0.f;
    __syncthreads();
    if (t == 0) g_is64 = !any;
}

// ---------------- normalize edge index + self loops + degree histogram ----------------
__global__ void convert_hist(const void* __restrict__ eiv) {
    int e = blockIdx.x * blockDim.x + threadIdx.x;
    if (e >= E2) return;
    int s, d;
    if (e >= EE) {
        s = d = e - EE;
    } else if (g_is64) {
        const long long* p = (const long long*)eiv;
        s = (int)p[e];
        d = (int)p[EE + e];
    } else {
        const int* p = (const int*)eiv;
        s = p[e];
        d = p[EE + e];
    }
    g_src[e] = s;
    g_dst[e] = d;
    g_rank[e] = atomicAdd(&g_deg[d], 1);
}

// ---------------- bump-allocator offsets (no scan needed) ----------------
__global__ void alloc_off() {
    int n = blockIdx.x * blockDim.x + threadIdx.x;
    if (n >= NN) return;
    g_off[n] = atomicAdd(&g_cursor, g_deg[n]);
}

__global__ void scatter_csr() {
    int e = blockIdx.x * blockDim.x + threadIdx.x;
    if (e >= E2) return;
    g_csr[g_off[g_dst[e]] + g_rank[e]] = g_src[e];
}

// ---------------- TF32 GEMM 128x128 + fused BN/PReLU pre-op + attn epilogue ----------------
__device__ __forceinline__ unsigned f2tf(float x) {
    unsigned r;
    asm("cvt.rna.tf32.f32 %0, %1;" : "=r"(r) : "f"(x));
    return r;
}

__device__ __forceinline__ float4 loadA4(const float* p) {
    return *(const float4*)p;
}
__device__ __forceinline__ float4 loadA4(const __half* p) {
    uint2 u = *(const uint2*)p;
    float2 f0 = __half22float2(*(__half2*)&u.x);
    float2 f1 = __half22float2(*(__half2*)&u.y);
    return make_float4(f0.x, f0.y, f1.x, f1.y);
}

template <typename TA>
__global__ __launch_bounds__(256) void gemm_tf32(
        const TA* __restrict__ A, const float* __restrict__ B,
        __half* __restrict__ C, const float* __restrict__ attS,
        const float* __restrict__ attD, int M,
        const float* __restrict__ scale, const float* __restrict__ shift,
        const float* __restrict__ pw) {
    extern __shared__ float sm[];
    float* sA = sm;
    float* sB = sm + 2 * ASZ;
    const int K = 256;
    int tid = threadIdx.x, lane = tid & 31, warp = tid >> 5;
    int wm = warp >> 1, wn = warp & 1;   // 4x2 warps, 32x64 per warp
    int g = lane >> 2, tg = lane & 3;
    int rowBase = blockIdx.y * BM;
    int colBase = blockIdx.x * BNT;
    int head = blockIdx.x * 2 + wn;      // each warp owns a full head
    float w = scale ? pw[0] : 0.f;

    float acc[2][8][4];
    #pragma unroll
    for (int mt = 0; mt < 2; mt++)
        #pragma unroll
        for (int nt = 0; nt < 8; nt++)
            #pragma unroll
            for (int i = 0; i < 4; i++) acc[mt][nt][i] = 0.f;

    float4 av[4], bv[4];
    auto loadA = [&](int k0) {
        #pragma unroll
        for (int i = 0; i < 4; i++) {
            int F = tid + i * 256;
            int r = rowBase + (F >> 3);
            int c = (F & 7) * 4;
            if (r < M) {
                float4 v = loadA4(A + (long)r * K + k0 + c);
                if (scale) {
                    float4 sc = *(const float4*)(scale + k0 + c);
                    float4 sh = *(const float4*)(shift + k0 + c);
                    v.x = fmaf(v.x, sc.x, sh.x); v.x = (v.x >= 0.f) ? v.x : w * v.x;
                    v.y = fmaf(v.y, sc.y, sh.y); v.y = (v.y >= 0.f) ? v.y : w * v.y;
                    v.z = fmaf(v.z, sc.z, sh.z); v.z = (v.z >= 0.f) ? v.z : w * v.z;
                    v.w = fmaf(v.w, sc.w, sh.w); v.w = (v.w >= 0.f) ? v.w : w * v.w;
                }
                av[i] = v;
            } else {
                av[i] = make_float4(0.f, 0.f, 0.f, 0.f);
            }
        }
        #pragma unroll
        for (int i = 0; i < 4; i++) {
            int F = tid + i * 256;
            int r = k0 + (F >> 5);
            int c = colBase + (F & 31) * 4;
            bv[i] = *(const float4*)(B + (long)r * HC + c);
        }
    };
    auto storeT = [&](int buf) {
        float* pA = sA + buf * ASZ;
        #pragma unroll
        for (int i = 0; i < 4; i++) {
            int F = tid + i * 256;
            int r = F >> 3, c = (F & 7) * 4;
            float4 v;
            v.x = __uint_as_float(f2tf(av[i].x));
            v.y = __uint_as_float(f2tf(av[i].y));
            v.z = __uint_as_float(f2tf(av[i].z));
            v.w = __uint_as_float(f2tf(av[i].w));
            *(float4*)(pA + r * ASTRIDE + c) = v;
        }
        float* pB = sB + buf * BSZ;
        #pragma unroll
        for (int i = 0; i < 4; i++) {
            int F = tid + i * 256;
            int r = F >> 5, c = (F & 31) * 4;
            float4 v;
            v.x = __uint_as_float(f2tf(bv[i].x));
            v.y = __uint_as_float(f2tf(bv[i].y));
            v.z = __uint_as_float(f2tf(bv[i].z));
            v.w = __uint_as_float(f2tf(bv[i].w));
            *(float4*)(pB + r * BSTRIDE + c) = v;
        }
    };

    loadA(0);
    storeT(0);
    __syncthreads();

    const int iters = K / BK;
    for (int it = 0; it < iters; it++) {
        int buf = it & 1;
        if (it + 1 < iters) loadA((it + 1) * BK);
        const float* pA = sA + buf * ASZ;
        const float* pB = sB + buf * BSZ;
        #pragma unroll
        for (int ks = 0; ks < 4; ks++) {
            int k = ks * 8;
            unsigned a[2][4], b[8][2];
            #pragma unroll
            for (int mt = 0; mt < 2; mt++) {
                int r0 = wm * 32 + mt * 16;
                a[mt][0] = __float_as_uint(pA[(r0 + g) * ASTRIDE + k + tg]);
                a[mt][1] = __float_as_uint(pA[(r0 + g + 8) * ASTRIDE + k + tg]);
                a[mt][2] = __float_as_uint(pA[(r0 + g) * ASTRIDE + k + tg + 4]);
                a[mt][3] = __float_as_uint(pA[(r0 + g + 8) * ASTRIDE + k + tg + 4]);
            }
            #pragma unroll
            for (int nt = 0; nt < 8; nt++) {
                int c0 = wn * 64 + nt * 8;
                b[nt][0] = __float_as_uint(pB[(k + tg) * BSTRIDE + c0 + g]);
                b[nt][1] = __float_as_uint(pB[(k + tg + 4) * BSTRIDE + c0 + g]);
            }
            #pragma unroll
            for (int mt = 0; mt < 2; mt++)
                #pragma unroll
                for (int nt = 0; nt < 8; nt++) {
                    asm volatile(
                        "mma.sync.aligned.m16n8k8.row.col.f32.tf32.tf32.f32 "
                        "{%0,%1,%2,%3}, {%4,%5,%6,%7}, {%8,%9}, {%0,%1,%2,%3};"
                        : "+f"(acc[mt][nt][0]), "+f"(acc[mt][nt][1]),
                          "+f"(acc[mt][nt][2]), "+f"(acc[mt][nt][3])
                        : "r"(a[mt][0]), "r"(a[mt][1]), "r"(a[mt][2]), "r"(a[mt][3]),
                          "r"(b[nt][0]), "r"(b[nt][1]));
                }
        }
        if (it + 1 < iters) storeT(buf ^ 1);
        __syncthreads();
    }

    // ---- C store (fp16) ----
    #pragma unroll
    for (int mt = 0; mt < 2; mt++) {
        int r = rowBase + wm * 32 + mt * 16 + g;
        #pragma unroll
        for (int nt = 0; nt < 8; nt++) {
            int c = colBase + wn * 64 + nt * 8 + tg * 2;
            if (r < M)
                *(__half2*)(C + (long)r * HC + c) =
                    __floats2half2_rn(acc[mt][nt][0], acc[mt][nt][1]);
            if (r + 8 < M)
                *(__half2*)(C + (long)(r + 8) * HC + c) =
                    __floats2half2_rn(acc[mt][nt][2], acc[mt][nt][3]);
        }
    }

    // ---- fused attention scores: warp-local (each warp owns one head) ----
    float ps0[2] = {0.f, 0.f}, ps1[2] = {0.f, 0.f};
    float pd0[2] = {0.f, 0.f}, pd1[2] = {0.f, 0.f};
    #pragma unroll
    for (int nt = 0; nt < 8; nt++) {
        int lc = nt * 8 + tg * 2;         // column within head
        float s0 = attS[head * HID + lc], s1 = attS[head * HID + lc + 1];
        float d0 = attD[head * HID + lc], d1 = attD[head * HID + lc + 1];
        #pragma unroll
        for (int mt = 0; mt < 2; mt++) {
            ps0[mt] += acc[mt][nt][0] * s0 + acc[mt][nt][1] * s1;
            ps1[mt] += acc[mt][nt][2] * s0 + acc[mt][nt][3] * s1;
            pd0[mt] += acc[mt][nt][0] * d0 + acc[mt][nt][1] * d1;
            pd1[mt] += acc[mt][nt][2] * d0 + acc[mt][nt][3] * d1;
        }
    }
    #pragma unroll
    for (int o = 1; o <= 2; o <<= 1) {
        #pragma unroll
        for (int mt = 0; mt < 2; mt++) {
            ps0[mt] += __shfl_xor_sync(0xffffffffu, ps0[mt], o);
            ps1[mt] += __shfl_xor_sync(0xffffffffu, ps1[mt], o);
            pd0[mt] += __shfl_xor_sync(0xffffffffu, pd0[mt], o);
            pd1[mt] += __shfl_xor_sync(0xffffffffu, pd1[mt], o);
        }
    }
    if (tg == 0) {
        #pragma unroll
        for (int mt = 0; mt < 2; mt++) {
            int r = rowBase + wm * 32 + mt * 16 + g;
            if (r < M) {
                g_as[r * HEADS + head] = ps0[mt];
                g_ad[r * HEADS + head] = pd0[mt];
            }
            if (r + 8 < M) {
                g_as[(r + 8) * HEADS + head] = ps1[mt];
                g_ad[(r + 8) * HEADS + head] = pd1[mt];
            }
        }
    }
}

// ---------------- CSR aggregation: warp per dst node + smem edge cache + fused BN stats ----------------
__device__ __forceinline__ void fma8(float* a, float al, uint4 v) {
    float2 f0 = __half22float2(*(__half2*)&v.x);
    float2 f1 = __half22float2(*(__half2*)&v.y);
    float2 f2 = __half22float2(*(__half2*)&v.z);
    float2 f3 = __half22float2(*(__half2*)&v.w);
    a[0] = fmaf(al, f0.x, a[0]); a[1] = fmaf(al, f0.y, a[1]);
    a[2] = fmaf(al, f1.x, a[2]); a[3] = fmaf(al, f1.y, a[3]);
    a[4] = fmaf(al, f2.x, a[4]); a[5] = fmaf(al, f2.y, a[5]);
    a[6] = fmaf(al, f3.x, a[6]); a[7] = fmaf(al, f3.y, a[7]);
}

// grid MUST be exactly NN*32/256 = 6250 blocks (all warps map to a valid node)
// meanHeads=0: outp16 = fp16 [NN,HC]; meanHeads=1: outp32 = fp32 [NN,HID]
__global__ __launch_bounds__(256) void agg_csr(const __half* __restrict__ hsrc,
                                               __half* __restrict__ outp16,
                                               float* __restrict__ outp32,
                                               int meanHeads) {
    __shared__ float sV[8][256];               // BN-stats staging (8 KB)
    __shared__ float sEx[8][ECACHE * 4];       // cached exp weights (8 KB)
    __shared__ int   sIdx[8][ECACHE];          // cached src indices (2 KB)
    int tid = threadIdx.x;
    int warp = tid >> 5;
    int lane = tid & 31;
    int d = (blockIdx.x * blockDim.x + tid) >> 5;
    int start = g_off[d];
    int deg = g_deg[d];
    int end = start + deg;
    float4 dv = *(const float4*)(g_ad + d * HEADS);
    float d0 = 0.f, d1 = 0.f, d2 = 0.f, d3 = 0.f;
    // pass 1: softmax denominator; cache (src, exp[4]) for first ECACHE edges
    for (int e = start + lane; e < end; e += 32) {
        int s = g_csr[e];
        float4 sv = *(const float4*)(g_as + s * HEADS);
        float l0 = sv.x + dv.x; l0 = fmaxf(l0, 0.2f * l0); float e0 = __expf(l0);
        float l1 = sv.y + dv.y; l1 = fmaxf(l1, 0.2f * l1); float e1 = __expf(l1);
        float l2 = sv.z + dv.z; l2 = fmaxf(l2, 0.2f * l2); float e2 = __expf(l2);
        float l3 = sv.w + dv.w; l3 = fmaxf(l3, 0.2f * l3); float e3 = __expf(l3);
        d0 += e0; d1 += e1; d2 += e2; d3 += e3;
        int i = e - start;
        if (i < ECACHE) {
            sIdx[warp][i] = s;
            *(float4*)&sEx[warp][i * 4] = make_float4(e0, e1, e2, e3);
        }
    }
    __syncwarp();
    #pragma unroll
    for (int o = 16; o > 0; o >>= 1) {
        d0 += __shfl_xor_sync(0xffffffffu, d0, o);
        d1 += __shfl_xor_sync(0xffffffffu, d1, o);
        d2 += __shfl_xor_sync(0xffffffffu, d2, o);
        d3 += __shfl_xor_sync(0xffffffffu, d3, o);
    }
    int hh = lane >> 3;            // lane covers channels [lane*8, lane*8+8)
    float dvh = (hh == 0) ? dv.x : (hh == 1) ? dv.y : (hh == 2) ? dv.z : dv.w;
    float den = (hh == 0) ? d0 : (hh == 1) ? d1 : (hh == 2) ? d2 : d3;
    float invh = 1.f / (den + 1e-16f);
    // pass 2: weighted gather; indices/weights from smem -> independent feature loads
    float a[8] = {0.f, 0.f, 0.f, 0.f, 0.f, 0.f, 0.f, 0.f};
    int cap = (deg < ECACHE) ? deg : ECACHE;
    int i = 0;
    for (; i + 4 <= cap; i += 4) {
        int s0 = sIdx[warp][i],     s1 = sIdx[warp][i + 1];
        int s2 = sIdx[warp][i + 2], s3 = sIdx[warp][i + 3];
        float w0 = sEx[warp][(i)     * 4 + hh];
        float w1 = sEx[warp][(i + 1) * 4 + hh];
        float w2 = sEx[warp][(i + 2) * 4 + hh];
        float w3 = sEx[warp][(i + 3) * 4 + hh];
        uint4 v0 = *((const uint4*)(hsrc + (long)s0 * HC) + lane);
        uint4 v1 = *((const uint4*)(hsrc + (long)s1 * HC) + lane);
        uint4 v2 = *((const uint4*)(hsrc + (long)s2 * HC) + lane);
        uint4 v3 = *((const uint4*)(hsrc + (long)s3 * HC) + lane);
        fma8(a, w0, v0);
        fma8(a, w1, v1);
        fma8(a, w2, v2);
        fma8(a, w3, v3);
    }
    for (; i < cap; i++) {
        int s0 = sIdx[warp][i];
        float w0 = sEx[warp][i * 4 + hh];
        uint4 v0 = *((const uint4*)(hsrc + (long)s0 * HC) + lane);
        fma8(a, w0, v0);
    }
    // spill path for deg > ECACHE (recompute, bitwise-identical weights)
    for (int e = start + ECACHE; e < end; e++) {
        int s0 = g_csr[e];
        float l0 = g_as[s0 * HEADS + hh] + dvh;
        l0 = fmaxf(l0, 0.2f * l0);
        uint4 v0 = *((const uint4*)(hsrc + (long)s0 * HC) + lane);
        fma8(a, __expf(l0), v0);
    }
    #pragma unroll
    for (int j = 0; j < 8; j++) a[j] *= invh;
    int bkt = blockIdx.x & (NBUCK - 1);
    if (!meanHeads) {
        // fp16 output (layer-2 GEMM input), 16B per lane
        uint4 ov;
        *(__half2*)&ov.x = __floats2half2_rn(a[0], a[1]);
        *(__half2*)&ov.y = __floats2half2_rn(a[2], a[3]);
        *(__half2*)&ov.z = __floats2half2_rn(a[4], a[5]);
        *(__half2*)&ov.w = __floats2half2_rn(a[6], a[7]);
        *((uint4*)(outp16 + (long)d * HC) + lane) = ov;
        #pragma unroll
        for (int j = 0; j < 8; j++) sV[warp][lane * 8 + j] = a[j];
        __syncthreads();
        int c = tid;   // 0..255
        float s = 0.f, q = 0.f;
        #pragma unroll
        for (int w = 0; w < 8; w++) {
            float v = sV[w][c];
            s += v;
            q += v * v;
        }
        atomicAdd(&g_statsB[bkt][c], s);
        atomicAdd(&g_statsB[bkt][256 + c], q);
    } else {
        // mean over heads: lanes L, L^8, L^16, L^24 hold same local channels
        #pragma unroll
        for (int j = 0; j < 8; j++) {
            a[j] += __shfl_xor_sync(0xffffffffu, a[j], 8);
            a[j] += __shfl_xor_sync(0xffffffffu, a[j], 16);
            a[j] *= 0.25f;
        }
        if (lane < 8) {
            float4* op = (float4*)(outp32 + (long)d * HID) + lane * 2;
            op[0] = make_float4(a[0], a[1], a[2], a[3]);
            op[1] = make_float4(a[4], a[5], a[6], a[7]);
            #pragma unroll
            for (int j = 0; j < 8; j++) sV[warp][lane * 8 + j] = a[j];
        }
        __syncthreads();
        if (tid < HID) {
            int c = tid;   // 0..63
            float s = 0.f, q = 0.f;
            #pragma unroll
            for (int w = 0; w < 8; w++) {
                float v = sV[w][c];
                s += v;
                q += v * v;
            }
            atomicAdd(&g_statsB[bkt][c], s);
            atomicAdd(&g_statsB[bkt][256 + c], q);
        }
    }
}

// ---------------- layer-1 BN affine from bucketed stats; re-zero buckets ----------------
__global__ void bn_finalize(const float* __restrict__ gamma,
                            const float* __restrict__ beta) {
    int c = threadIdx.x;   // 0..255
    float s = 0.f, q = 0.f;
    #pragma unroll
    for (int b = 0; b < NBUCK; b++) {
        s += g_statsB[b][c];
        q += g_statsB[b][256 + c];
    }
    float invN = 1.f / (float)NN;
    float mean = s * invN;
    float var = q * invN - mean * mean;
    float sc = gamma[c] * rsqrtf(var + 1e-5f);
    g_scale[c] = sc;
    g_shift[c] = beta[c] - mean * sc;
    #pragma unroll
    for (int b = 0; b < NBUCK; b++) {
        g_statsB[b][c] = 0.f;
        g_statsB[b][256 + c] = 0.f;
    }
}

// ---------------- layer-2 BN affine (y path, 64 channels) ----------------
__global__ void bn_finalize2(const float* __restrict__ gamma,
                             const float* __restrict__ beta) {
    int c = threadIdx.x;
    if (c >= HID) return;
    float s = 0.f, q = 0.f;
    #pragma unroll
    for (int b = 0; b < NBUCK; b++) {
        s += g_statsB[b][c];
        q += g_statsB[b][256 + c];
    }
    float invN = 1.f / (float)NN;
    float mean = s * invN;
    float var = q * invN - mean * mean;
    float sc = gamma[c] * rsqrtf(var + 1e-5f);
    g_scale2[c] = sc;
    g_shift2[c] = beta[c] - mean * sc;
}

// ---------------- fused BN2-affine + ELU + final linear ----------------
__global__ __launch_bounds__(256) void fc_fused(const float* __restrict__ W,
                                                const float* __restrict__ b,
                                                float* __restrict__ out) {
    __shared__ float sW[HID * OUTD];   // 21.5 KB
    __shared__ float sY[32 * HID];     // 8 KB
    int tid = threadIdx.x;
    for (int l = tid; l < HID * OUTD; l += 256)
        sW[l] = W[l];
    int n0 = blockIdx.x * 32;
    for (int i = tid; i < 32 * HID; i += 256) {
        int n = n0 + (i >> 6), c = i & (HID - 1);
        float v = 0.f;
        if (n < NN) {
            v = g_y[(long)n * HID + c] * g_scale2[c] + g_shift2[c];
            v = (v > 0.f) ? v : expm1f(v);
        }
        sY[i] = v;
    }
    __syncthreads();
    for (int j = tid; j < 32 * OUTD; j += 256) {
        int nl = j / OUTD, o = j - nl * OUTD;
        int n = n0 + nl;
        if (n >= NN) continue;
        const float* y = sY + nl * HID;
        float acc = b[o];
        #pragma unroll
        for (int k = 0; k < HID; k++)
            acc += y[k] * sW[k * OUTD + o];
        out[(long)n * OUTD + o] = acc;
    }
}

extern "C" void kernel_launch(void* const* d_in, const int* in_sizes, int n_in,
                              void* d_out, int out_size) {
    const float* x   = (const float*)d_in[0];
    const void*  ei  = d_in[1];
    const float* W1  = (const float*)d_in[2];
    const float* as1 = (const float*)d_in[3];
    const float* ad1 = (const float*)d_in[4];
    const float* W2  = (const float*)d_in[6];
    const float* as2 = (const float*)d_in[7];
    const float* ad2 = (const float*)d_in[8];
    const float* g1  = (const float*)d_in[10];
    const float* be1 = (const float*)d_in[11];
    const float* g2  = (const float*)d_in[12];
    const float* be2 = (const float*)d_in[13];
    const float* pw  = (const float*)d_in[14];
    const float* fcW = (const float*)d_in[15];
    const float* fcb = (const float*)d_in[16];
    float* out = (float*)d_out;

    __half *p_h, *p_aggh;
    float *p_y, *p_scale, *p_shift;
    cudaGetSymbolAddress((void**)&p_h, g_h);
    cudaGetSymbolAddress((void**)&p_aggh, g_aggh);
    cudaGetSymbolAddress((void**)&p_y, g_y);
    cudaGetSymbolAddress((void**)&p_scale, g_scale);
    cudaGetSymbolAddress((void**)&p_shift, g_shift);

    static cudaStream_t s2 = nullptr;
    static cudaEvent_t evFork = nullptr, evJoin = nullptr;
    static int init_done = 0;
    if (!init_done) {
        cudaFuncSetAttribute(gemm_tf32<float>,
                             cudaFuncAttributeMaxDynamicSharedMemorySize, GEMM_SMEM);
        cudaFuncSetAttribute(gemm_tf32<__half>,
                             cudaFuncAttributeMaxDynamicSharedMemorySize, GEMM_SMEM);
        cudaStreamCreateWithFlags(&s2, cudaStreamNonBlocking);
        cudaEventCreateWithFlags(&evFork, cudaEventDisableTiming);
        cudaEventCreateWithFlags(&evJoin, cudaEventDisableTiming);
        init_done = 1;
    }

    dim3 gemmGrid(HC / BNT, (NN + BM - 1) / BM);   // (2, 391)
    int edgeBlocks = (E2 + 255) / 256;
    int aggBlocks  = NN * 32 / 256;                 // 6250 exact

    // ---- fork: CSR build (+ bucket zeroing) on side stream, concurrent with GEMM1 ----
    cudaEventRecord(evFork, 0);
    cudaStreamWaitEvent(s2, evFork, 0);
    detect_dtype<<<1, 256, 0, s2>>>((const int*)ei);
    convert_hist<<<edgeBlocks, 256, 0, s2>>>(ei);
    alloc_off<<<(NN + 255) / 256, 256, 0, s2>>>();
    scatter_csr<<<edgeBlocks, 256, 0, s2>>>();
    cudaEventRecord(evJoin, s2);

    // ---- layer 1 GEMM (main stream, independent of CSR) ----
    gemm_tf32<float><<<gemmGrid, 256, GEMM_SMEM>>>(x, W1, p_h, as1, ad1, NN,
                                                   nullptr, nullptr, nullptr);

    // ---- join: aggregation needs both; BN1 stats fused into agg ----
    cudaStreamWaitEvent(0, evJoin, 0);
    agg_csr<<<aggBlocks, 256>>>(p_h, p_aggh, nullptr, 0);
    bn_finalize<<<1, 256>>>(g1, be1);

    // ---- layer 2 (BN1 affine + PReLU fused into GEMM A-load; head-mean + BN2 stats fused into agg) ----
    gemm_tf32<__half><<<gemmGrid, 256, GEMM_SMEM>>>(p_aggh, W2, p_h, as2, ad2, NN,
                                                    p_scale, p_shift, pw);
    agg_csr<<<aggBlocks, 256>>>(p_h, nullptr, p_y, 1);
    bn_finalize2<<<1, 64>>>(g2, be2);
    fc_fused<<<(NN + 31) / 32, 256>>>(fcW, fcb, out);
}